// round 15
// baseline (speedup 1.0000x reference)
#include <cuda_runtime.h>
#include <cuda_bf16.h>
#include <cuda_fp16.h>
#include <math.h>
#include <stdint.h>

// ---------------- problem constants ----------------
#define T_DIM   2048
#define HID     5120
#define QLR     1536
#define KVLR    512
#define NOPE    128
#define ROPE_D  64
#define VDIM    128
#define H_HEADS 32
#define QKD     192
#define DQK     576
#define QKV_N   (QLR + DQK)     // 2112
#define ATTN_SCALE 0.07216878364870323f
#define RMS_EPS 1e-6f

#define STAGES 3
#define BK 32
#define ROW_U32 20
#define ROW_BYTES 80
#define ARR_U32 (128 * ROW_U32)               // 2560
#define STAGE_U32 (4 * ARR_U32)               // 10240
#define SMEM_BYTES (STAGES * STAGE_U32 * 4)   // 122880
#define F16_STAGE_U32 (3 * ARR_U32)           // 7680 (A single + Bh + Bl)
#define F16_SMEM_BYTES (STAGES * F16_STAGE_U32 * 4)  // 92160

// ---------------- fp32 scratch ----------------
__device__ float g_qalat [T_DIM * QKV_N];
__device__ float g_kin   [T_DIM * DQK];
__device__ float g_cs    [T_DIM * ROPE_D];
__device__ float g_scores[134217728];       // [H][T][T]

// ---------------- split-bf16 operand storage (hi/lo) ----------------
#define BDECL(name, n) \
    __device__ __align__(16) __nv_bfloat16 name##_h[n]; \
    __device__ __align__(16) __nv_bfloat16 name##_l[n];

BDECL(b_hid,    10485760)
BDECL(b_wqkvT,  10813440)
BDECL(b_qan,     3145728)
BDECL(b_wqbT,    9437184)
BDECL(b_qproj,  12582912)
BDECL(b_wkcT,    2097152)
BDECL(b_qin,    37748736)
BDECL(b_kin,     1179648)
BDECL(b_ctx,    33554432)
BDECL(b_wvcT,    2097152)
BDECL(b_attn,    8388608)
BDECL(b_woT,    20971520)

// ---------------- fp16 probs path storage ----------------
__device__ __align__(16) __half h_probs[134217728];  // [32][2048][2048]
__device__ __align__(16) __half h_vT_h [1048576];    // [512][2048]
__device__ __align__(16) __half h_vT_l [1048576];

// ---------------- helpers ----------------
__device__ __forceinline__ void split1(float x, __nv_bfloat16& h, __nv_bfloat16& l)
{
    h = __float2bfloat16(x);
    l = __float2bfloat16(x - __bfloat162float(h));
}
__device__ __forceinline__ void split1h(float x, __half& h, __half& l)
{
    h = __float2half(x);
    l = __float2half(x - __half2float(h));
}
__device__ __forceinline__ uint32_t packbf(__nv_bfloat16 a, __nv_bfloat16 b)
{
    return (uint32_t)__bfloat16_as_ushort(a) | ((uint32_t)__bfloat16_as_ushort(b) << 16);
}
__device__ __forceinline__ void cp16(void* smem_dst, const void* gsrc)
{
    uint32_t d = (uint32_t)__cvta_generic_to_shared(smem_dst);
    asm volatile("cp.async.ca.shared.global [%0], [%1], 16;" :: "r"(d), "l"(gsrc));
}
#define CP_COMMIT() asm volatile("cp.async.commit_group;")
#define CP_WAIT()   asm volatile("cp.async.wait_group 1;")

#define MMA16816(c, a, b)                                                      \
    asm volatile("mma.sync.aligned.m16n8k16.row.col.f32.bf16.bf16.f32 "        \
                 "{%0,%1,%2,%3},{%4,%5,%6,%7},{%8,%9},{%0,%1,%2,%3};"          \
                 : "+f"((c)[0]), "+f"((c)[1]), "+f"((c)[2]), "+f"((c)[3])      \
                 : "r"((a)[0]), "r"((a)[1]), "r"((a)[2]), "r"((a)[3]),         \
                   "r"((b)[0]), "r"((b)[1]))

#define MMA16816F(c, a, b)                                                     \
    asm volatile("mma.sync.aligned.m16n8k16.row.col.f32.f16.f16.f32 "          \
                 "{%0,%1,%2,%3},{%4,%5,%6,%7},{%8,%9},{%0,%1,%2,%3};"          \
                 : "+f"((c)[0]), "+f"((c)[1]), "+f"((c)[2]), "+f"((c)[3])      \
                 : "r"((a)[0]), "r"((a)[1]), "r"((a)[2]), "r"((a)[3]),         \
                   "r"((b)[0]), "r"((b)[1]))

#define LDSM4(r, a)                                                            \
    asm volatile("ldmatrix.sync.aligned.m8n8.x4.shared.b16 {%0,%1,%2,%3}, [%4];" \
                 : "=r"((r)[0]), "=r"((r)[1]), "=r"((r)[2]), "=r"((r)[3])      \
                 : "r"(a))

// ---------------- split-bf16 TN GEMM (ldmatrix fragments) ----------------
template <int CAUSAL, bool SPLITOUT>
__global__ __launch_bounds__(256)
void gemm_bf16(const __nv_bfloat16* __restrict__ Ah, const __nv_bfloat16* __restrict__ Al,
               const __nv_bfloat16* __restrict__ Bh, const __nv_bfloat16* __restrict__ Bl,
               float* __restrict__ C,
               __nv_bfloat16* __restrict__ CH, __nv_bfloat16* __restrict__ CL,
               int M, int N, int K, int lda, int ldb, int ldc,
               long long sA, long long sB, long long sC, float alpha)
{
    const int m0 = blockIdx.y * 128;
    const int n0 = blockIdx.x * 128;
    if (CAUSAL == 1 && n0 > m0 + 127) return;

    Ah += (long long)blockIdx.z * sA;  Al += (long long)blockIdx.z * sA;
    Bh += (long long)blockIdx.z * sB;  Bl += (long long)blockIdx.z * sB;
    if (SPLITOUT) { CH += (long long)blockIdx.z * sC; CL += (long long)blockIdx.z * sC; }
    else          { C  += (long long)blockIdx.z * sC; }

    const int Keff = (CAUSAL == 2) ? min(K, m0 + 128) : K;
    const int nk = Keff / BK;

    extern __shared__ uint32_t smem_u[];
    const uint32_t sm_base = (uint32_t)__cvta_generic_to_shared(smem_u);

    const int tid  = threadIdx.x;
    const int lane = tid & 31;
    const int warp = tid >> 5;
    const int gid  = lane >> 2;
    const int tig  = lane & 3;
    const int warpM = (warp & 1) * 64;
    const int warpN = (warp >> 1) * 32;

    const int r0 = tid >> 2;
    const int c0 = tid & 3;

    const int q  = lane >> 3;
    const int ri = lane & 7;
    uint32_t aOff[4];
#pragma unroll
    for (int i = 0; i < 4; i++)
        aOff[i] = (uint32_t)((warpM + i * 16 + (q & 1) * 8 + ri) * ROW_BYTES + (q >> 1) * 16);
    uint32_t bOff[2];
#pragma unroll
    for (int jp = 0; jp < 2; jp++)
        bOff[jp] = (uint32_t)((warpN + (2 * jp + (q >> 1)) * 8 + ri) * ROW_BYTES + (q & 1) * 16);

    auto load_stage = [&](int slot, int k0) {
        uint32_t* base = smem_u + slot * STAGE_U32;
#pragma unroll
        for (int u = 0; u < 2; u++) {
            int row = r0 + u * 64;
            int kc  = k0 + c0 * 8;
            uint32_t* dA = base + row * ROW_U32 + c0 * 4;
            cp16(dA,             Ah + (long long)(m0 + row) * lda + kc);
            cp16(dA + ARR_U32,   Al + (long long)(m0 + row) * lda + kc);
            int bn = min(n0 + row, N - 1);
            uint32_t* dB = base + 2 * ARR_U32 + row * ROW_U32 + c0 * 4;
            cp16(dB,             Bh + (long long)bn * ldb + kc);
            cp16(dB + ARR_U32,   Bl + (long long)bn * ldb + kc);
        }
    };

    float acc[4][4][4];
#pragma unroll
    for (int i = 0; i < 4; i++)
#pragma unroll
        for (int j = 0; j < 4; j++)
#pragma unroll
            for (int c = 0; c < 4; c++) acc[i][j][c] = 0.f;

    for (int s = 0; s < STAGES - 1; s++) {
        if (s < nk) load_stage(s, s * BK);
        CP_COMMIT();
    }

    for (int it = 0; it < nk; it++) {
        CP_WAIT();
        __syncthreads();

        if (it + STAGES - 1 < nk)
            load_stage((it + STAGES - 1) % STAGES, (it + STAGES - 1) * BK);
        CP_COMMIT();

        const uint32_t stA_h = sm_base + (it % STAGES) * STAGE_U32 * 4;
        const uint32_t stA_l = stA_h + ARR_U32 * 4;
        const uint32_t stB_h = stA_h + 2 * ARR_U32 * 4;
        const uint32_t stB_l = stA_h + 3 * ARR_U32 * 4;

#pragma unroll
        for (int ks = 0; ks < 2; ks++) {
            const uint32_t cbB = ks * 32;
            uint32_t af[4][4], bh4[4][2], bl4[4][2];
#pragma unroll
            for (int i = 0; i < 4; i++)
                LDSM4(af[i], stA_h + aOff[i] + cbB);
#pragma unroll
            for (int jp = 0; jp < 2; jp++) {
                LDSM4(&bh4[2 * jp][0], stB_h + bOff[jp] + cbB);
                LDSM4(&bl4[2 * jp][0], stB_l + bOff[jp] + cbB);
            }
#pragma unroll
            for (int i = 0; i < 4; i++)
#pragma unroll
                for (int j = 0; j < 4; j++) {
                    MMA16816(acc[i][j], af[i], bh4[j]);
                    MMA16816(acc[i][j], af[i], bl4[j]);
                }
#pragma unroll
            for (int i = 0; i < 4; i++)
                LDSM4(af[i], stA_l + aOff[i] + cbB);
#pragma unroll
            for (int i = 0; i < 4; i++)
#pragma unroll
                for (int j = 0; j < 4; j++)
                    MMA16816(acc[i][j], af[i], bh4[j]);
        }
        __syncthreads();
    }

#pragma unroll
    for (int i = 0; i < 4; i++) {
#pragma unroll
        for (int j = 0; j < 4; j++) {
            int r = m0 + warpM + i * 16 + gid;
            int cn = n0 + warpN + j * 8 + 2 * tig;
            if (cn < N) {
                if (SPLITOUT) {
#pragma unroll
                    for (int rr = 0; rr < 2; rr++) {
                        __nv_bfloat16 h0, l0, h1, l1;
                        split1(acc[i][j][rr * 2 + 0] * alpha, h0, l0);
                        split1(acc[i][j][rr * 2 + 1] * alpha, h1, l1);
                        long long o = (long long)(r + rr * 8) * ldc + cn;
                        *(uint32_t*)(CH + o) = packbf(h0, h1);
                        *(uint32_t*)(CL + o) = packbf(l0, l1);
                    }
                } else {
                    float2 v0 = make_float2(acc[i][j][0] * alpha, acc[i][j][1] * alpha);
                    float2 v1 = make_float2(acc[i][j][2] * alpha, acc[i][j][3] * alpha);
                    *(float2*)(C + (long long)r * ldc + cn)       = v0;
                    *(float2*)(C + (long long)(r + 8) * ldc + cn) = v1;
                }
            }
        }
    }
}

// ---------------- fp16 TN GEMM: A single fp16, B fp16 hi/lo (2 MMAs) --------
// Used for ctx = probs @ v^T. Output split-bf16.
template <int CAUSAL>
__global__ __launch_bounds__(256)
void gemm_f16(const __half* __restrict__ A,
              const __half* __restrict__ Bh, const __half* __restrict__ Bl,
              __nv_bfloat16* __restrict__ CH, __nv_bfloat16* __restrict__ CL,
              int M, int N, int K, int lda, int ldb, int ldc,
              long long sA, long long sB, long long sC, float alpha)
{
    const int m0 = blockIdx.y * 128;
    const int n0 = blockIdx.x * 128;

    A  += (long long)blockIdx.z * sA;
    Bh += (long long)blockIdx.z * sB;  Bl += (long long)blockIdx.z * sB;
    CH += (long long)blockIdx.z * sC;  CL += (long long)blockIdx.z * sC;

    const int Keff = (CAUSAL == 2) ? min(K, m0 + 128) : K;
    const int nk = Keff / BK;

    extern __shared__ uint32_t smem_u[];
    const uint32_t sm_base = (uint32_t)__cvta_generic_to_shared(smem_u);

    const int tid  = threadIdx.x;
    const int lane = tid & 31;
    const int warp = tid >> 5;
    const int gid  = lane >> 2;
    const int tig  = lane & 3;
    const int warpM = (warp & 1) * 64;
    const int warpN = (warp >> 1) * 32;

    const int r0 = tid >> 2;
    const int c0 = tid & 3;

    const int q  = lane >> 3;
    const int ri = lane & 7;
    uint32_t aOff[4];
#pragma unroll
    for (int i = 0; i < 4; i++)
        aOff[i] = (uint32_t)((warpM + i * 16 + (q & 1) * 8 + ri) * ROW_BYTES + (q >> 1) * 16);
    uint32_t bOff[2];
#pragma unroll
    for (int jp = 0; jp < 2; jp++)
        bOff[jp] = (uint32_t)((warpN + (2 * jp + (q >> 1)) * 8 + ri) * ROW_BYTES + (q & 1) * 16);

    auto load_stage = [&](int slot, int k0) {
        uint32_t* base = smem_u + slot * F16_STAGE_U32;
#pragma unroll
        for (int u = 0; u < 2; u++) {
            int row = r0 + u * 64;
            int kc  = k0 + c0 * 8;
            uint32_t* dA = base + row * ROW_U32 + c0 * 4;
            cp16(dA, A + (long long)(m0 + row) * lda + kc);
            int bn = min(n0 + row, N - 1);
            uint32_t* dB = base + ARR_U32 + row * ROW_U32 + c0 * 4;
            cp16(dB,             Bh + (long long)bn * ldb + kc);
            cp16(dB + ARR_U32,   Bl + (long long)bn * ldb + kc);
        }
    };

    float acc[4][4][4];
#pragma unroll
    for (int i = 0; i < 4; i++)
#pragma unroll
        for (int j = 0; j < 4; j++)
#pragma unroll
            for (int c = 0; c < 4; c++) acc[i][j][c] = 0.f;

    for (int s = 0; s < STAGES - 1; s++) {
        if (s < nk) load_stage(s, s * BK);
        CP_COMMIT();
    }

    for (int it = 0; it < nk; it++) {
        CP_WAIT();
        __syncthreads();

        if (it + STAGES - 1 < nk)
            load_stage((it + STAGES - 1) % STAGES, (it + STAGES - 1) * BK);
        CP_COMMIT();

        const uint32_t stA   = sm_base + (it % STAGES) * F16_STAGE_U32 * 4;
        const uint32_t stB_h = stA + ARR_U32 * 4;
        const uint32_t stB_l = stA + 2 * ARR_U32 * 4;

#pragma unroll
        for (int ks = 0; ks < 2; ks++) {
            const uint32_t cbB = ks * 32;
            uint32_t af[4][4], bh4[4][2], bl4[4][2];
#pragma unroll
            for (int i = 0; i < 4; i++)
                LDSM4(af[i], stA + aOff[i] + cbB);
#pragma unroll
            for (int jp = 0; jp < 2; jp++) {
                LDSM4(&bh4[2 * jp][0], stB_h + bOff[jp] + cbB);
                LDSM4(&bl4[2 * jp][0], stB_l + bOff[jp] + cbB);
            }
#pragma unroll
            for (int i = 0; i < 4; i++)
#pragma unroll
                for (int j = 0; j < 4; j++) {
                    MMA16816F(acc[i][j], af[i], bh4[j]);
                    MMA16816F(acc[i][j], af[i], bl4[j]);
                }
        }
        __syncthreads();
    }

#pragma unroll
    for (int i = 0; i < 4; i++) {
#pragma unroll
        for (int j = 0; j < 4; j++) {
            int r = m0 + warpM + i * 16 + gid;
            int cn = n0 + warpN + j * 8 + 2 * tig;
            if (cn < N) {
#pragma unroll
                for (int rr = 0; rr < 2; rr++) {
                    __nv_bfloat16 h0, l0, h1, l1;
                    split1(acc[i][j][rr * 2 + 0] * alpha, h0, l0);
                    split1(acc[i][j][rr * 2 + 1] * alpha, h1, l1);
                    long long o = (long long)(r + rr * 8) * ldc + cn;
                    *(uint32_t*)(CH + o) = packbf(h0, h1);
                    *(uint32_t*)(CL + o) = packbf(l0, l1);
                }
            }
        }
    }
}

// ---------------- convert: fp32 row-major -> split bf16 ----------------------
__global__ void convert_row_split(const float* __restrict__ in,
                                  __nv_bfloat16* __restrict__ oh,
                                  __nv_bfloat16* __restrict__ ol)
{
    long long idx = ((long long)blockIdx.x * 256 + threadIdx.x) * 4;
    float4 f = *(const float4*)(in + idx);
    __nv_bfloat16 h[4], l[4];
    split1(f.x, h[0], l[0]); split1(f.y, h[1], l[1]);
    split1(f.z, h[2], l[2]); split1(f.w, h[3], l[3]);
    *(uint2*)(oh + idx) = *(uint2*)h;
    *(uint2*)(ol + idx) = *(uint2*)l;
}

// ---------------- transpose: fp32 [R][C] -> split bf16 [C][R] ----------------
__global__ void transpose_split(const float* __restrict__ in, int ldin,
                                int R, int Ccols,
                                __nv_bfloat16* __restrict__ oh,
                                __nv_bfloat16* __restrict__ ol,
                                long long sIn, long long sOut)
{
    __shared__ float tile[32][33];
    in += (long long)blockIdx.z * sIn;
    oh += (long long)blockIdx.z * sOut;
    ol += (long long)blockIdx.z * sOut;
    const int cb = blockIdx.x * 32;
    const int rb = blockIdx.y * 32;
#pragma unroll
    for (int i = 0; i < 4; i++) {
        int r = rb + threadIdx.y + i * 8;
        int c = cb + threadIdx.x;
        tile[threadIdx.y + i * 8][threadIdx.x] =
            (r < R && c < Ccols) ? in[(long long)r * ldin + c] : 0.f;
    }
    __syncthreads();
#pragma unroll
    for (int i = 0; i < 4; i++) {
        int c = cb + threadIdx.y + i * 8;
        int r = rb + threadIdx.x;
        if (c < Ccols && r < R) {
            __nv_bfloat16 h, l;
            split1(tile[threadIdx.x][threadIdx.y + i * 8], h, l);
            oh[(long long)c * R + r] = h;
            ol[(long long)c * R + r] = l;
        }
    }
}

// ---------------- transpose: fp32 [R][C] -> split fp16 [C][R] ----------------
__global__ void transpose_split_f16(const float* __restrict__ in, int ldin,
                                    int R, int Ccols,
                                    __half* __restrict__ oh,
                                    __half* __restrict__ ol)
{
    __shared__ float tile[32][33];
    const int cb = blockIdx.x * 32;
    const int rb = blockIdx.y * 32;
#pragma unroll
    for (int i = 0; i < 4; i++) {
        int r = rb + threadIdx.y + i * 8;
        int c = cb + threadIdx.x;
        tile[threadIdx.y + i * 8][threadIdx.x] =
            (r < R && c < Ccols) ? in[(long long)r * ldin + c] : 0.f;
    }
    __syncthreads();
#pragma unroll
    for (int i = 0; i < 4; i++) {
        int c = cb + threadIdx.y + i * 8;
        int r = rb + threadIdx.x;
        if (c < Ccols && r < R) {
            __half h, l;
            split1h(tile[threadIdx.x][threadIdx.y + i * 8], h, l);
            oh[(long long)c * R + r] = h;
            ol[(long long)c * R + r] = l;
        }
    }
}

// ---------------- RMSNorm (strided input) with fused split output ------------
__global__ void rmsnorm_split(const float* __restrict__ x, int ldx,
                              const float* __restrict__ w,
                              __nv_bfloat16* __restrict__ yh,
                              __nv_bfloat16* __restrict__ yl, int D)
{
    const int row = blockIdx.x;
    const float* xr = x + (long long)row * ldx;

    float ss = 0.f;
    for (int i = threadIdx.x; i < D; i += 256) { float v = xr[i]; ss += v * v; }
    __shared__ float red[256];
    red[threadIdx.x] = ss;
    __syncthreads();
    for (int s = 128; s > 0; s >>= 1) {
        if (threadIdx.x < s) red[threadIdx.x] += red[threadIdx.x + s];
        __syncthreads();
    }
    const float r = rsqrtf(red[0] / (float)D + RMS_EPS);
    for (int i = threadIdx.x; i < D; i += 256) {
        __nv_bfloat16 h, l;
        split1(xr[i] * r * w[i], h, l);
        yh[(long long)row * D + i] = h;
        yl[(long long)row * D + i] = l;
    }
}

// ---------------- build k_input (fp32 + split) + cos/sin ---------------------
__global__ void build_k_kernel(const float* __restrict__ qalat,
                               const float* __restrict__ w,
                               const int* __restrict__ pos32,
                               float* __restrict__ kin,
                               __nv_bfloat16* __restrict__ kh,
                               __nv_bfloat16* __restrict__ kl,
                               float* __restrict__ cs)
{
    const int t = blockIdx.x;
    const float* lr = qalat + (long long)t * QKV_N + QLR;
    float* kr       = kin   + (long long)t * DQK;

    float ss = 0.f;
    for (int i = threadIdx.x; i < KVLR; i += 256) { float v = lr[i]; ss += v * v; }
    __shared__ float red[256];
    red[threadIdx.x] = ss;
    __syncthreads();
    for (int s = 128; s > 0; s >>= 1) {
        if (threadIdx.x < s) red[threadIdx.x] += red[threadIdx.x + s];
        __syncthreads();
    }
    const float r = rsqrtf(red[0] / (float)KVLR + RMS_EPS);
    for (int i = threadIdx.x; i < KVLR; i += 256) {
        float v = lr[i] * r * w[i];
        kr[i] = v;
        __nv_bfloat16 h, l;
        split1(v, h, l);
        kh[(long long)t * DQK + i] = h;
        kl[(long long)t * DQK + i] = l;
    }

    if (threadIdx.x < 32) {
        const int j = threadIdx.x;
        const bool is64 = (pos32[1] == 0);
        const long long p = is64 ? ((const long long*)pos32)[t]
                                 : (long long)pos32[t];
        const double inv = pow(10000.0, -(double)(2 * j) / (double)ROPE_D);
        const double ang = (double)p * inv;
        const float c = (float)cos(ang);
        const float s = (float)sin(ang);
        cs[t * ROPE_D + j]      = c;
        cs[t * ROPE_D + 32 + j] = s;
        const float x1 = lr[KVLR + 2 * j];
        const float x2 = lr[KVLR + 2 * j + 1];
        float o1 = x1 * c - x2 * s;
        float o2 = x2 * c + x1 * s;
        kr[KVLR + 2 * j]     = o1;
        kr[KVLR + 2 * j + 1] = o2;
        __nv_bfloat16 h0, l0, h1, l1;
        split1(o1, h0, l0); split1(o2, h1, l1);
        *(uint32_t*)(kh + (long long)t * DQK + KVLR + 2 * j) = packbf(h0, h1);
        *(uint32_t*)(kl + (long long)t * DQK + KVLR + 2 * j) = packbf(l0, l1);
    }
}

// ---------------- rope q_pe: split qproj -> split qin[.., 512:576] -----------
__global__ void rope_q_split(const __nv_bfloat16* __restrict__ qh,
                             const __nv_bfloat16* __restrict__ ql,
                             const float* __restrict__ cs,
                             __nv_bfloat16* __restrict__ oh,
                             __nv_bfloat16* __restrict__ ol)
{
    const int t = blockIdx.x;
    const int h = blockIdx.y * blockDim.y + threadIdx.y;
    const int j = threadIdx.x;

    const float c = cs[t * ROPE_D + j];
    const float s = cs[t * ROPE_D + 32 + j];
    long long qoff = (long long)t * (H_HEADS * QKD) + h * QKD + NOPE + 2 * j;
    uint32_t ph = *(const uint32_t*)(qh + qoff);
    uint32_t pl = *(const uint32_t*)(ql + qoff);
    float x1 = __bfloat162float(__ushort_as_bfloat16((unsigned short)(ph & 0xFFFF)))
             + __bfloat162float(__ushort_as_bfloat16((unsigned short)(pl & 0xFFFF)));
    float x2 = __bfloat162float(__ushort_as_bfloat16((unsigned short)(ph >> 16)))
             + __bfloat162float(__ushort_as_bfloat16((unsigned short)(pl >> 16)));
    float o1 = x1 * c - x2 * s;
    float o2 = x2 * c + x1 * s;
    __nv_bfloat16 h0, l0, h1, l1;
    split1(o1, h0, l0); split1(o2, h1, l1);
    long long o = ((long long)h * T_DIM + t) * DQK + KVLR + 2 * j;
    *(uint32_t*)(oh + o) = packbf(h0, h1);
    *(uint32_t*)(ol + o) = packbf(l0, l1);
}

// ---------------- causal softmax (register-cached) -> single fp16 ------------
__global__ void softmax_f16(const float* __restrict__ scores,
                            __half* __restrict__ pr)
{
    const int t = blockIdx.x;
    const int h = blockIdx.y;
    const long long off = ((long long)h * T_DIM + t) * T_DIM;
    const float* row = scores + off;
    const int len = t + 1;

    __shared__ float red[256];
    float rv[8];

#pragma unroll
    for (int c = 0; c < 8; c++) {
        int i = threadIdx.x + c * 256;
        rv[c] = (i < len) ? row[i] : -1e30f;
    }
    float mx = rv[0];
#pragma unroll
    for (int c = 1; c < 8; c++) mx = fmaxf(mx, rv[c]);
    red[threadIdx.x] = mx;
    __syncthreads();
    for (int s = 128; s > 0; s >>= 1) {
        if (threadIdx.x < s) red[threadIdx.x] = fmaxf(red[threadIdx.x], red[threadIdx.x + s]);
        __syncthreads();
    }
    mx = red[0];
    __syncthreads();

    float sum = 0.f;
#pragma unroll
    for (int c = 0; c < 8; c++) {
        int i = threadIdx.x + c * 256;
        rv[c] = (i < len) ? expf(rv[c] - mx) : 0.f;
        sum += rv[c];
    }
    red[threadIdx.x] = sum;
    __syncthreads();
    for (int s = 128; s > 0; s >>= 1) {
        if (threadIdx.x < s) red[threadIdx.x] += red[threadIdx.x + s];
        __syncthreads();
    }
    const float inv = 1.f / red[0];

#pragma unroll
    for (int c = 0; c < 8; c++) {
        int i = threadIdx.x + c * 256;
        if (i < len) pr[off + i] = __float2half(rv[c] * inv);
    }
    const int zend = min(T_DIM, ((t >> 7) + 1) << 7);
    const __half z = __float2half(0.f);
    for (int i = len + threadIdx.x; i < zend; i += 256) pr[off + i] = z;
}

// ---------------- launch ------------------------------------------------------
#define SYM(p, s) cudaGetSymbolAddress((void**)&p, s)

extern "C" void kernel_launch(void* const* d_in, const int* in_sizes, int n_in,
                              void* d_out, int out_size)
{
    const float* hidden    = (const float*)d_in[0];
    const int*   positions = (const int*)d_in[1];
    const float* w_q_a     = (const float*)d_in[2];
    const float* q_a_ln_w  = (const float*)d_in[3];
    const float* w_q_b     = (const float*)d_in[4];
    const float* w_kv_a    = (const float*)d_in[5];
    const float* kv_a_ln_w = (const float*)d_in[6];
    const float* w_kc      = (const float*)d_in[7];
    const float* w_vc      = (const float*)d_in[8];
    const float* w_o       = (const float*)d_in[9];
    float*       out       = (float*)d_out;

    float *qalat, *kin, *cs, *scores;
    SYM(qalat, g_qalat); SYM(kin, g_kin); SYM(cs, g_cs); SYM(scores, g_scores);

    __nv_bfloat16 *hid_h,*hid_l, *wqkvT_h,*wqkvT_l, *qan_h,*qan_l, *wqbT_h,*wqbT_l,
                  *qpr_h,*qpr_l, *wkcT_h,*wkcT_l, *qin_h,*qin_l,
                  *kin_h,*kin_l, *ctx_h,*ctx_l,
                  *wvcT_h,*wvcT_l, *att_h,*att_l, *woT_h,*woT_l;
    __half *pr16, *vT16_h, *vT16_l;
    SYM(hid_h,b_hid_h);     SYM(hid_l,b_hid_l);
    SYM(wqkvT_h,b_wqkvT_h); SYM(wqkvT_l,b_wqkvT_l);
    SYM(qan_h,b_qan_h);     SYM(qan_l,b_qan_l);
    SYM(wqbT_h,b_wqbT_h);   SYM(wqbT_l,b_wqbT_l);
    SYM(qpr_h,b_qproj_h);   SYM(qpr_l,b_qproj_l);
    SYM(wkcT_h,b_wkcT_h);   SYM(wkcT_l,b_wkcT_l);
    SYM(qin_h,b_qin_h);     SYM(qin_l,b_qin_l);
    SYM(kin_h,b_kin_h);     SYM(kin_l,b_kin_l);
    SYM(ctx_h,b_ctx_h);     SYM(ctx_l,b_ctx_l);
    SYM(wvcT_h,b_wvcT_h);   SYM(wvcT_l,b_wvcT_l);
    SYM(att_h,b_attn_h);    SYM(att_l,b_attn_l);
    SYM(woT_h,b_woT_h);     SYM(woT_l,b_woT_l);
    SYM(pr16, h_probs);     SYM(vT16_h, h_vT_h);  SYM(vT16_l, h_vT_l);

    cudaFuncSetAttribute(gemm_bf16<0,false>, cudaFuncAttributeMaxDynamicSharedMemorySize, SMEM_BYTES);
    cudaFuncSetAttribute(gemm_bf16<0,true >, cudaFuncAttributeMaxDynamicSharedMemorySize, SMEM_BYTES);
    cudaFuncSetAttribute(gemm_bf16<1,false>, cudaFuncAttributeMaxDynamicSharedMemorySize, SMEM_BYTES);
    cudaFuncSetAttribute(gemm_f16<2>, cudaFuncAttributeMaxDynamicSharedMemorySize, F16_SMEM_BYTES);

    dim3 tb(32, 8);

    // ---- operand conversion (weights + hidden) ----
    convert_row_split<<<10240, 256>>>(hidden, hid_h, hid_l);
    transpose_split<<<dim3(48, 160, 1), tb>>>(w_q_a, QLR, HID, QLR, wqkvT_h, wqkvT_l, 0, 0);
    transpose_split<<<dim3(18, 160, 1), tb>>>(w_kv_a, DQK, HID, DQK,
                                              wqkvT_h + (long long)QLR * HID,
                                              wqkvT_l + (long long)QLR * HID, 0, 0);
    transpose_split<<<dim3(192, 48, 1), tb>>>(w_q_b, H_HEADS*QKD, QLR, H_HEADS*QKD, wqbT_h, wqbT_l, 0, 0);
    transpose_split<<<dim3(16, 4, H_HEADS), tb>>>(w_kc, KVLR, NOPE, KVLR, wkcT_h, wkcT_l,
                                                  (long long)NOPE*KVLR, (long long)KVLR*NOPE);
    transpose_split<<<dim3(4, 16, H_HEADS), tb>>>(w_vc, VDIM, KVLR, VDIM, wvcT_h, wvcT_l,
                                                  (long long)KVLR*VDIM, (long long)VDIM*KVLR);
    transpose_split<<<dim3(160, 128, 1), tb>>>(w_o, HID, H_HEADS*VDIM, HID, woT_h, woT_l, 0, 0);

    // 1+4. [q_a | latent] = hidden @ [w_q_a | w_kv_a]  (merged, fp32 out)
    gemm_bf16<0,false><<<dim3(17, 16, 1), 256, SMEM_BYTES>>>(
        hid_h, hid_l, wqkvT_h, wqkvT_l, qalat, nullptr, nullptr,
        T_DIM, QKV_N, HID, HID, HID, QKV_N, 0, 0, 0, 1.f);
    // 2. rmsnorm(q_a) -> split
    rmsnorm_split<<<T_DIM, 256>>>(qalat, QKV_N, q_a_ln_w, qan_h, qan_l, QLR);
    // 5. k_input (fp32 + split) + cos/sin; vT fp16 split from fp32 kin
    build_k_kernel<<<T_DIM, 256>>>(qalat, kv_a_ln_w, positions, kin, kin_h, kin_l, cs);
    transpose_split_f16<<<dim3(16, 64, 1), tb>>>(kin, DQK, T_DIM, KVLR, vT16_h, vT16_l);
    // 3. qproj = qan @ w_q_b  (split out)
    gemm_bf16<0,true><<<dim3(48, 16, 1), 256, SMEM_BYTES>>>(
        qan_h, qan_l, wqbT_h, wqbT_l, nullptr, qpr_h, qpr_l,
        T_DIM, H_HEADS*QKD, QLR, QLR, QLR, H_HEADS*QKD, 0, 0, 0, 1.f);
    // 6. qin[:, :512] = q_nope @ w_kc  (split out, strided into qin)
    gemm_bf16<0,true><<<dim3(4, 16, H_HEADS), 256, SMEM_BYTES>>>(
        qpr_h, qpr_l, wkcT_h, wkcT_l, nullptr, qin_h, qin_l,
        T_DIM, KVLR, NOPE, H_HEADS*QKD, NOPE, DQK,
        (long long)QKD, (long long)KVLR*NOPE, (long long)T_DIM*DQK, 1.f);
    // 7. qin[:, 512:576] = rope(q_pe)
    rope_q_split<<<dim3(T_DIM, H_HEADS/8), dim3(32, 8)>>>(qpr_h, qpr_l, cs, qin_h, qin_l);
    // 8. scores = SCALE * qin @ kin^T  (causal skip, fp32 out)
    gemm_bf16<1,false><<<dim3(16, 16, H_HEADS), 256, SMEM_BYTES>>>(
        qin_h, qin_l, kin_h, kin_l, scores, nullptr, nullptr,
        T_DIM, T_DIM, DQK, DQK, DQK, T_DIM,
        (long long)T_DIM*DQK, 0, (long long)T_DIM*T_DIM, ATTN_SCALE);
    // 9. softmax -> single fp16 probs
    softmax_f16<<<dim3(T_DIM, H_HEADS), 256>>>(scores, pr16);
    // 10. ctx = probs @ v  (fp16 path: 2 MMAs; K clamped; split-bf16 out)
    gemm_f16<2><<<dim3(4, 16, H_HEADS), 256, F16_SMEM_BYTES>>>(
        pr16, vT16_h, vT16_l, ctx_h, ctx_l,
        T_DIM, KVLR, T_DIM, T_DIM, T_DIM, KVLR,
        (long long)T_DIM*T_DIM, 0, (long long)T_DIM*KVLR, 1.f);
    // 11. attn = ctx @ w_vc  (split out)
    gemm_bf16<0,true><<<dim3(1, 16, H_HEADS), 256, SMEM_BYTES>>>(
        ctx_h, ctx_l, wvcT_h, wvcT_l, nullptr, att_h, att_l,
        T_DIM, VDIM, KVLR, KVLR, KVLR, H_HEADS*VDIM,
        (long long)T_DIM*KVLR, (long long)VDIM*KVLR, (long long)VDIM, 1.f);
    // 12. out = attn @ w_o  (fp32 out)
    gemm_bf16<0,false><<<dim3(40, 16, 1), 256, SMEM_BYTES>>>(
        att_h, att_l, woT_h, woT_l, out, nullptr, nullptr,
        T_DIM, HID, H_HEADS*VDIM, H_HEADS*VDIM, H_HEADS*VDIM, HID, 0, 0, 0, 1.f);
}

// round 16
// speedup vs baseline: 1.0012x; 1.0012x over previous
#include <cuda_runtime.h>
#include <cuda_bf16.h>
#include <cuda_fp16.h>
#include <math.h>
#include <stdint.h>

// ---------------- problem constants ----------------
#define T_DIM   2048
#define HID     5120
#define QLR     1536
#define KVLR    512
#define NOPE    128
#define ROPE_D  64
#define VDIM    128
#define H_HEADS 32
#define QKD     192
#define DQK     576
#define QKV_N   (QLR + DQK)     // 2112
#define ATTN_SCALE 0.07216878364870323f
#define RMS_EPS 1e-6f

#define STAGES 3
#define BK 32
#define ROW_U32 20
#define ROW_BYTES 80
#define ARR_U32 (128 * ROW_U32)               // 2560
#define STAGE_U32 (4 * ARR_U32)               // 10240
#define SMEM_BYTES (STAGES * STAGE_U32 * 4)   // 122880
#define F16_STAGE_U32 (3 * ARR_U32)           // 7680 (A single + Bh + Bl)
#define F16_SMEM_BYTES (STAGES * F16_STAGE_U32 * 4)  // 92160

// ---------------- fp32 scratch ----------------
__device__ float g_qalat [T_DIM * QKV_N];
__device__ float g_kin   [T_DIM * DQK];
__device__ float g_cs    [T_DIM * ROPE_D];
__device__ float g_scores[134217728];       // [H][T][T]

// ---------------- split-bf16 operand storage (hi/lo) ----------------
#define BDECL(name, n) \
    __device__ __align__(16) __nv_bfloat16 name##_h[n]; \
    __device__ __align__(16) __nv_bfloat16 name##_l[n];

BDECL(b_hid,    10485760)
BDECL(b_wqkvT,  10813440)
BDECL(b_qan,     3145728)
BDECL(b_wqbT,    9437184)
BDECL(b_qproj,  12582912)
BDECL(b_wkcT,    2097152)
BDECL(b_qin,    37748736)
BDECL(b_kin,     1179648)
BDECL(b_ctx,    33554432)
BDECL(b_wvcT,    2097152)
BDECL(b_attn,    8388608)
BDECL(b_woT,    20971520)

// ---------------- fp16 probs path storage ----------------
__device__ __align__(16) __half h_probs[134217728];  // [32][2048][2048]
__device__ __align__(16) __half h_vT_h [1048576];    // [512][2048]
__device__ __align__(16) __half h_vT_l [1048576];

// ---------------- helpers ----------------
__device__ __forceinline__ void split1(float x, __nv_bfloat16& h, __nv_bfloat16& l)
{
    h = __float2bfloat16(x);
    l = __float2bfloat16(x - __bfloat162float(h));
}
__device__ __forceinline__ void split1h(float x, __half& h, __half& l)
{
    h = __float2half(x);
    l = __float2half(x - __half2float(h));
}
__device__ __forceinline__ uint32_t packbf(__nv_bfloat16 a, __nv_bfloat16 b)
{
    return (uint32_t)__bfloat16_as_ushort(a) | ((uint32_t)__bfloat16_as_ushort(b) << 16);
}
__device__ __forceinline__ void cp16(void* smem_dst, const void* gsrc)
{
    uint32_t d = (uint32_t)__cvta_generic_to_shared(smem_dst);
    asm volatile("cp.async.ca.shared.global [%0], [%1], 16;" :: "r"(d), "l"(gsrc));
}
#define CP_COMMIT() asm volatile("cp.async.commit_group;")
#define CP_WAIT()   asm volatile("cp.async.wait_group 1;")

#define MMA16816(c, a, b)                                                      \
    asm volatile("mma.sync.aligned.m16n8k16.row.col.f32.bf16.bf16.f32 "        \
                 "{%0,%1,%2,%3},{%4,%5,%6,%7},{%8,%9},{%0,%1,%2,%3};"          \
                 : "+f"((c)[0]), "+f"((c)[1]), "+f"((c)[2]), "+f"((c)[3])      \
                 : "r"((a)[0]), "r"((a)[1]), "r"((a)[2]), "r"((a)[3]),         \
                   "r"((b)[0]), "r"((b)[1]))

#define MMA16816F(c, a, b)                                                     \
    asm volatile("mma.sync.aligned.m16n8k16.row.col.f32.f16.f16.f32 "          \
                 "{%0,%1,%2,%3},{%4,%5,%6,%7},{%8,%9},{%0,%1,%2,%3};"          \
                 : "+f"((c)[0]), "+f"((c)[1]), "+f"((c)[2]), "+f"((c)[3])      \
                 : "r"((a)[0]), "r"((a)[1]), "r"((a)[2]), "r"((a)[3]),         \
                   "r"((b)[0]), "r"((b)[1]))

#define LDSM4(r, a)                                                            \
    asm volatile("ldmatrix.sync.aligned.m8n8.x4.shared.b16 {%0,%1,%2,%3}, [%4];" \
                 : "=r"((r)[0]), "=r"((r)[1]), "=r"((r)[2]), "=r"((r)[3])      \
                 : "r"(a))

// ---------------- split-bf16 TN GEMM (ldmatrix fragments) ----------------
template <int CAUSAL, bool SPLITOUT>
__global__ __launch_bounds__(256)
void gemm_bf16(const __nv_bfloat16* __restrict__ Ah, const __nv_bfloat16* __restrict__ Al,
               const __nv_bfloat16* __restrict__ Bh, const __nv_bfloat16* __restrict__ Bl,
               float* __restrict__ C,
               __nv_bfloat16* __restrict__ CH, __nv_bfloat16* __restrict__ CL,
               int M, int N, int K, int lda, int ldb, int ldc,
               long long sA, long long sB, long long sC, float alpha)
{
    const int m0 = blockIdx.y * 128;
    const int n0 = blockIdx.x * 128;
    if (CAUSAL == 1 && n0 > m0 + 127) return;

    Ah += (long long)blockIdx.z * sA;  Al += (long long)blockIdx.z * sA;
    Bh += (long long)blockIdx.z * sB;  Bl += (long long)blockIdx.z * sB;
    if (SPLITOUT) { CH += (long long)blockIdx.z * sC; CL += (long long)blockIdx.z * sC; }
    else          { C  += (long long)blockIdx.z * sC; }

    const int Keff = (CAUSAL == 2) ? min(K, m0 + 128) : K;
    const int nk = Keff / BK;

    extern __shared__ uint32_t smem_u[];
    const uint32_t sm_base = (uint32_t)__cvta_generic_to_shared(smem_u);

    const int tid  = threadIdx.x;
    const int lane = tid & 31;
    const int warp = tid >> 5;
    const int gid  = lane >> 2;
    const int tig  = lane & 3;
    const int warpM = (warp & 1) * 64;
    const int warpN = (warp >> 1) * 32;

    const int r0 = tid >> 2;
    const int c0 = tid & 3;

    const int q  = lane >> 3;
    const int ri = lane & 7;
    uint32_t aOff[4];
#pragma unroll
    for (int i = 0; i < 4; i++)
        aOff[i] = (uint32_t)((warpM + i * 16 + (q & 1) * 8 + ri) * ROW_BYTES + (q >> 1) * 16);
    uint32_t bOff[2];
#pragma unroll
    for (int jp = 0; jp < 2; jp++)
        bOff[jp] = (uint32_t)((warpN + (2 * jp + (q >> 1)) * 8 + ri) * ROW_BYTES + (q & 1) * 16);

    auto load_stage = [&](int slot, int k0) {
        uint32_t* base = smem_u + slot * STAGE_U32;
#pragma unroll
        for (int u = 0; u < 2; u++) {
            int row = r0 + u * 64;
            int kc  = k0 + c0 * 8;
            uint32_t* dA = base + row * ROW_U32 + c0 * 4;
            cp16(dA,             Ah + (long long)(m0 + row) * lda + kc);
            cp16(dA + ARR_U32,   Al + (long long)(m0 + row) * lda + kc);
            int bn = min(n0 + row, N - 1);
            uint32_t* dB = base + 2 * ARR_U32 + row * ROW_U32 + c0 * 4;
            cp16(dB,             Bh + (long long)bn * ldb + kc);
            cp16(dB + ARR_U32,   Bl + (long long)bn * ldb + kc);
        }
    };

    float acc[4][4][4];
#pragma unroll
    for (int i = 0; i < 4; i++)
#pragma unroll
        for (int j = 0; j < 4; j++)
#pragma unroll
            for (int c = 0; c < 4; c++) acc[i][j][c] = 0.f;

    for (int s = 0; s < STAGES - 1; s++) {
        if (s < nk) load_stage(s, s * BK);
        CP_COMMIT();
    }

    for (int it = 0; it < nk; it++) {
        CP_WAIT();
        __syncthreads();

        if (it + STAGES - 1 < nk)
            load_stage((it + STAGES - 1) % STAGES, (it + STAGES - 1) * BK);
        CP_COMMIT();

        const uint32_t stA_h = sm_base + (it % STAGES) * STAGE_U32 * 4;
        const uint32_t stA_l = stA_h + ARR_U32 * 4;
        const uint32_t stB_h = stA_h + 2 * ARR_U32 * 4;
        const uint32_t stB_l = stA_h + 3 * ARR_U32 * 4;

#pragma unroll
        for (int ks = 0; ks < 2; ks++) {
            const uint32_t cbB = ks * 32;
            uint32_t af[4][4], bh4[4][2], bl4[4][2];
#pragma unroll
            for (int i = 0; i < 4; i++)
                LDSM4(af[i], stA_h + aOff[i] + cbB);
#pragma unroll
            for (int jp = 0; jp < 2; jp++) {
                LDSM4(&bh4[2 * jp][0], stB_h + bOff[jp] + cbB);
                LDSM4(&bl4[2 * jp][0], stB_l + bOff[jp] + cbB);
            }
#pragma unroll
            for (int i = 0; i < 4; i++)
#pragma unroll
                for (int j = 0; j < 4; j++) {
                    MMA16816(acc[i][j], af[i], bh4[j]);
                    MMA16816(acc[i][j], af[i], bl4[j]);
                }
#pragma unroll
            for (int i = 0; i < 4; i++)
                LDSM4(af[i], stA_l + aOff[i] + cbB);
#pragma unroll
            for (int i = 0; i < 4; i++)
#pragma unroll
                for (int j = 0; j < 4; j++)
                    MMA16816(acc[i][j], af[i], bh4[j]);
        }
        __syncthreads();
    }

#pragma unroll
    for (int i = 0; i < 4; i++) {
#pragma unroll
        for (int j = 0; j < 4; j++) {
            int r = m0 + warpM + i * 16 + gid;
            int cn = n0 + warpN + j * 8 + 2 * tig;
            if (cn < N) {
                if (SPLITOUT) {
#pragma unroll
                    for (int rr = 0; rr < 2; rr++) {
                        __nv_bfloat16 h0, l0, h1, l1;
                        split1(acc[i][j][rr * 2 + 0] * alpha, h0, l0);
                        split1(acc[i][j][rr * 2 + 1] * alpha, h1, l1);
                        long long o = (long long)(r + rr * 8) * ldc + cn;
                        *(uint32_t*)(CH + o) = packbf(h0, h1);
                        *(uint32_t*)(CL + o) = packbf(l0, l1);
                    }
                } else {
                    float2 v0 = make_float2(acc[i][j][0] * alpha, acc[i][j][1] * alpha);
                    float2 v1 = make_float2(acc[i][j][2] * alpha, acc[i][j][3] * alpha);
                    *(float2*)(C + (long long)r * ldc + cn)       = v0;
                    *(float2*)(C + (long long)(r + 8) * ldc + cn) = v1;
                }
            }
        }
    }
}

// ---------------- fp16 TN GEMM: A single fp16, B fp16 hi/lo (2 MMAs) --------
// Used for ctx = probs @ v^T. Output split-bf16.
template <int CAUSAL>
__global__ __launch_bounds__(256)
void gemm_f16(const __half* __restrict__ A,
              const __half* __restrict__ Bh, const __half* __restrict__ Bl,
              __nv_bfloat16* __restrict__ CH, __nv_bfloat16* __restrict__ CL,
              int M, int N, int K, int lda, int ldb, int ldc,
              long long sA, long long sB, long long sC, float alpha)
{
    const int m0 = blockIdx.y * 128;
    const int n0 = blockIdx.x * 128;

    A  += (long long)blockIdx.z * sA;
    Bh += (long long)blockIdx.z * sB;  Bl += (long long)blockIdx.z * sB;
    CH += (long long)blockIdx.z * sC;  CL += (long long)blockIdx.z * sC;

    const int Keff = (CAUSAL == 2) ? min(K, m0 + 128) : K;
    const int nk = Keff / BK;

    extern __shared__ uint32_t smem_u[];
    const uint32_t sm_base = (uint32_t)__cvta_generic_to_shared(smem_u);

    const int tid  = threadIdx.x;
    const int lane = tid & 31;
    const int warp = tid >> 5;
    const int gid  = lane >> 2;
    const int tig  = lane & 3;
    const int warpM = (warp & 1) * 64;
    const int warpN = (warp >> 1) * 32;

    const int r0 = tid >> 2;
    const int c0 = tid & 3;

    const int q  = lane >> 3;
    const int ri = lane & 7;
    uint32_t aOff[4];
#pragma unroll
    for (int i = 0; i < 4; i++)
        aOff[i] = (uint32_t)((warpM + i * 16 + (q & 1) * 8 + ri) * ROW_BYTES + (q >> 1) * 16);
    uint32_t bOff[2];
#pragma unroll
    for (int jp = 0; jp < 2; jp++)
        bOff[jp] = (uint32_t)((warpN + (2 * jp + (q >> 1)) * 8 + ri) * ROW_BYTES + (q & 1) * 16);

    auto load_stage = [&](int slot, int k0) {
        uint32_t* base = smem_u + slot * F16_STAGE_U32;
#pragma unroll
        for (int u = 0; u < 2; u++) {
            int row = r0 + u * 64;
            int kc  = k0 + c0 * 8;
            uint32_t* dA = base + row * ROW_U32 + c0 * 4;
            cp16(dA, A + (long long)(m0 + row) * lda + kc);
            int bn = min(n0 + row, N - 1);
            uint32_t* dB = base + ARR_U32 + row * ROW_U32 + c0 * 4;
            cp16(dB,             Bh + (long long)bn * ldb + kc);
            cp16(dB + ARR_U32,   Bl + (long long)bn * ldb + kc);
        }
    };

    float acc[4][4][4];
#pragma unroll
    for (int i = 0; i < 4; i++)
#pragma unroll
        for (int j = 0; j < 4; j++)
#pragma unroll
            for (int c = 0; c < 4; c++) acc[i][j][c] = 0.f;

    for (int s = 0; s < STAGES - 1; s++) {
        if (s < nk) load_stage(s, s * BK);
        CP_COMMIT();
    }

    for (int it = 0; it < nk; it++) {
        CP_WAIT();
        __syncthreads();

        if (it + STAGES - 1 < nk)
            load_stage((it + STAGES - 1) % STAGES, (it + STAGES - 1) * BK);
        CP_COMMIT();

        const uint32_t stA   = sm_base + (it % STAGES) * F16_STAGE_U32 * 4;
        const uint32_t stB_h = stA + ARR_U32 * 4;
        const uint32_t stB_l = stA + 2 * ARR_U32 * 4;

#pragma unroll
        for (int ks = 0; ks < 2; ks++) {
            const uint32_t cbB = ks * 32;
            uint32_t af[4][4], bh4[4][2], bl4[4][2];
#pragma unroll
            for (int i = 0; i < 4; i++)
                LDSM4(af[i], stA + aOff[i] + cbB);
#pragma unroll
            for (int jp = 0; jp < 2; jp++) {
                LDSM4(&bh4[2 * jp][0], stB_h + bOff[jp] + cbB);
                LDSM4(&bl4[2 * jp][0], stB_l + bOff[jp] + cbB);
            }
#pragma unroll
            for (int i = 0; i < 4; i++)
#pragma unroll
                for (int j = 0; j < 4; j++) {
                    MMA16816F(acc[i][j], af[i], bh4[j]);
                    MMA16816F(acc[i][j], af[i], bl4[j]);
                }
        }
        __syncthreads();
    }

#pragma unroll
    for (int i = 0; i < 4; i++) {
#pragma unroll
        for (int j = 0; j < 4; j++) {
            int r = m0 + warpM + i * 16 + gid;
            int cn = n0 + warpN + j * 8 + 2 * tig;
            if (cn < N) {
#pragma unroll
                for (int rr = 0; rr < 2; rr++) {
                    __nv_bfloat16 h0, l0, h1, l1;
                    split1(acc[i][j][rr * 2 + 0] * alpha, h0, l0);
                    split1(acc[i][j][rr * 2 + 1] * alpha, h1, l1);
                    long long o = (long long)(r + rr * 8) * ldc + cn;
                    *(uint32_t*)(CH + o) = packbf(h0, h1);
                    *(uint32_t*)(CL + o) = packbf(l0, l1);
                }
            }
        }
    }
}

// ---------------- convert: fp32 row-major -> split bf16 ----------------------
__global__ void convert_row_split(const float* __restrict__ in,
                                  __nv_bfloat16* __restrict__ oh,
                                  __nv_bfloat16* __restrict__ ol)
{
    long long idx = ((long long)blockIdx.x * 256 + threadIdx.x) * 4;
    float4 f = *(const float4*)(in + idx);
    __nv_bfloat16 h[4], l[4];
    split1(f.x, h[0], l[0]); split1(f.y, h[1], l[1]);
    split1(f.z, h[2], l[2]); split1(f.w, h[3], l[3]);
    *(uint2*)(oh + idx) = *(uint2*)h;
    *(uint2*)(ol + idx) = *(uint2*)l;
}

// ---------------- transpose: fp32 [R][C] -> split bf16 [C][R] ----------------
__global__ void transpose_split(const float* __restrict__ in, int ldin,
                                int R, int Ccols,
                                __nv_bfloat16* __restrict__ oh,
                                __nv_bfloat16* __restrict__ ol,
                                long long sIn, long long sOut)
{
    __shared__ float tile[32][33];
    in += (long long)blockIdx.z * sIn;
    oh += (long long)blockIdx.z * sOut;
    ol += (long long)blockIdx.z * sOut;
    const int cb = blockIdx.x * 32;
    const int rb = blockIdx.y * 32;
#pragma unroll
    for (int i = 0; i < 4; i++) {
        int r = rb + threadIdx.y + i * 8;
        int c = cb + threadIdx.x;
        tile[threadIdx.y + i * 8][threadIdx.x] =
            (r < R && c < Ccols) ? in[(long long)r * ldin + c] : 0.f;
    }
    __syncthreads();
#pragma unroll
    for (int i = 0; i < 4; i++) {
        int c = cb + threadIdx.y + i * 8;
        int r = rb + threadIdx.x;
        if (c < Ccols && r < R) {
            __nv_bfloat16 h, l;
            split1(tile[threadIdx.x][threadIdx.y + i * 8], h, l);
            oh[(long long)c * R + r] = h;
            ol[(long long)c * R + r] = l;
        }
    }
}

// ---------------- transpose: fp32 [R][C] -> split fp16 [C][R] ----------------
__global__ void transpose_split_f16(const float* __restrict__ in, int ldin,
                                    int R, int Ccols,
                                    __half* __restrict__ oh,
                                    __half* __restrict__ ol)
{
    __shared__ float tile[32][33];
    const int cb = blockIdx.x * 32;
    const int rb = blockIdx.y * 32;
#pragma unroll
    for (int i = 0; i < 4; i++) {
        int r = rb + threadIdx.y + i * 8;
        int c = cb + threadIdx.x;
        tile[threadIdx.y + i * 8][threadIdx.x] =
            (r < R && c < Ccols) ? in[(long long)r * ldin + c] : 0.f;
    }
    __syncthreads();
#pragma unroll
    for (int i = 0; i < 4; i++) {
        int c = cb + threadIdx.y + i * 8;
        int r = rb + threadIdx.x;
        if (c < Ccols && r < R) {
            __half h, l;
            split1h(tile[threadIdx.x][threadIdx.y + i * 8], h, l);
            oh[(long long)c * R + r] = h;
            ol[(long long)c * R + r] = l;
        }
    }
}

// ---------------- RMSNorm (strided input) with fused split output ------------
__global__ void rmsnorm_split(const float* __restrict__ x, int ldx,
                              const float* __restrict__ w,
                              __nv_bfloat16* __restrict__ yh,
                              __nv_bfloat16* __restrict__ yl, int D)
{
    const int row = blockIdx.x;
    const float* xr = x + (long long)row * ldx;

    float ss = 0.f;
    for (int i = threadIdx.x; i < D; i += 256) { float v = xr[i]; ss += v * v; }
    __shared__ float red[256];
    red[threadIdx.x] = ss;
    __syncthreads();
    for (int s = 128; s > 0; s >>= 1) {
        if (threadIdx.x < s) red[threadIdx.x] += red[threadIdx.x + s];
        __syncthreads();
    }
    const float r = rsqrtf(red[0] / (float)D + RMS_EPS);
    for (int i = threadIdx.x; i < D; i += 256) {
        __nv_bfloat16 h, l;
        split1(xr[i] * r * w[i], h, l);
        yh[(long long)row * D + i] = h;
        yl[(long long)row * D + i] = l;
    }
}

// ---------------- build k_input (fp32 + split) + cos/sin ---------------------
__global__ void build_k_kernel(const float* __restrict__ qalat,
                               const float* __restrict__ w,
                               const int* __restrict__ pos32,
                               float* __restrict__ kin,
                               __nv_bfloat16* __restrict__ kh,
                               __nv_bfloat16* __restrict__ kl,
                               float* __restrict__ cs)
{
    const int t = blockIdx.x;
    const float* lr = qalat + (long long)t * QKV_N + QLR;
    float* kr       = kin   + (long long)t * DQK;

    float ss = 0.f;
    for (int i = threadIdx.x; i < KVLR; i += 256) { float v = lr[i]; ss += v * v; }
    __shared__ float red[256];
    red[threadIdx.x] = ss;
    __syncthreads();
    for (int s = 128; s > 0; s >>= 1) {
        if (threadIdx.x < s) red[threadIdx.x] += red[threadIdx.x + s];
        __syncthreads();
    }
    const float r = rsqrtf(red[0] / (float)KVLR + RMS_EPS);
    for (int i = threadIdx.x; i < KVLR; i += 256) {
        float v = lr[i] * r * w[i];
        kr[i] = v;
        __nv_bfloat16 h, l;
        split1(v, h, l);
        kh[(long long)t * DQK + i] = h;
        kl[(long long)t * DQK + i] = l;
    }

    if (threadIdx.x < 32) {
        const int j = threadIdx.x;
        const bool is64 = (pos32[1] == 0);
        const long long p = is64 ? ((const long long*)pos32)[t]
                                 : (long long)pos32[t];
        const double inv = pow(10000.0, -(double)(2 * j) / (double)ROPE_D);
        const double ang = (double)p * inv;
        const float c = (float)cos(ang);
        const float s = (float)sin(ang);
        cs[t * ROPE_D + j]      = c;
        cs[t * ROPE_D + 32 + j] = s;
        const float x1 = lr[KVLR + 2 * j];
        const float x2 = lr[KVLR + 2 * j + 1];
        float o1 = x1 * c - x2 * s;
        float o2 = x2 * c + x1 * s;
        kr[KVLR + 2 * j]     = o1;
        kr[KVLR + 2 * j + 1] = o2;
        __nv_bfloat16 h0, l0, h1, l1;
        split1(o1, h0, l0); split1(o2, h1, l1);
        *(uint32_t*)(kh + (long long)t * DQK + KVLR + 2 * j) = packbf(h0, h1);
        *(uint32_t*)(kl + (long long)t * DQK + KVLR + 2 * j) = packbf(l0, l1);
    }
}

// ---------------- rope q_pe: split qproj -> split qin[.., 512:576] -----------
__global__ void rope_q_split(const __nv_bfloat16* __restrict__ qh,
                             const __nv_bfloat16* __restrict__ ql,
                             const float* __restrict__ cs,
                             __nv_bfloat16* __restrict__ oh,
                             __nv_bfloat16* __restrict__ ol)
{
    const int t = blockIdx.x;
    const int h = blockIdx.y * blockDim.y + threadIdx.y;
    const int j = threadIdx.x;

    const float c = cs[t * ROPE_D + j];
    const float s = cs[t * ROPE_D + 32 + j];
    long long qoff = (long long)t * (H_HEADS * QKD) + h * QKD + NOPE + 2 * j;
    uint32_t ph = *(const uint32_t*)(qh + qoff);
    uint32_t pl = *(const uint32_t*)(ql + qoff);
    float x1 = __bfloat162float(__ushort_as_bfloat16((unsigned short)(ph & 0xFFFF)))
             + __bfloat162float(__ushort_as_bfloat16((unsigned short)(pl & 0xFFFF)));
    float x2 = __bfloat162float(__ushort_as_bfloat16((unsigned short)(ph >> 16)))
             + __bfloat162float(__ushort_as_bfloat16((unsigned short)(pl >> 16)));
    float o1 = x1 * c - x2 * s;
    float o2 = x2 * c + x1 * s;
    __nv_bfloat16 h0, l0, h1, l1;
    split1(o1, h0, l0); split1(o2, h1, l1);
    long long o = ((long long)h * T_DIM + t) * DQK + KVLR + 2 * j;
    *(uint32_t*)(oh + o) = packbf(h0, h1);
    *(uint32_t*)(ol + o) = packbf(l0, l1);
}

// ---------------- causal softmax (register-cached) -> single fp16 ------------
__global__ void softmax_f16(const float* __restrict__ scores,
                            __half* __restrict__ pr)
{
    const int t = blockIdx.x;
    const int h = blockIdx.y;
    const long long off = ((long long)h * T_DIM + t) * T_DIM;
    const float* row = scores + off;
    const int len = t + 1;

    __shared__ float red[256];
    float rv[8];

#pragma unroll
    for (int c = 0; c < 8; c++) {
        int i = threadIdx.x + c * 256;
        rv[c] = (i < len) ? row[i] : -1e30f;
    }
    float mx = rv[0];
#pragma unroll
    for (int c = 1; c < 8; c++) mx = fmaxf(mx, rv[c]);
    red[threadIdx.x] = mx;
    __syncthreads();
    for (int s = 128; s > 0; s >>= 1) {
        if (threadIdx.x < s) red[threadIdx.x] = fmaxf(red[threadIdx.x], red[threadIdx.x + s]);
        __syncthreads();
    }
    mx = red[0];
    __syncthreads();

    float sum = 0.f;
#pragma unroll
    for (int c = 0; c < 8; c++) {
        int i = threadIdx.x + c * 256;
        rv[c] = (i < len) ? expf(rv[c] - mx) : 0.f;
        sum += rv[c];
    }
    red[threadIdx.x] = sum;
    __syncthreads();
    for (int s = 128; s > 0; s >>= 1) {
        if (threadIdx.x < s) red[threadIdx.x] += red[threadIdx.x + s];
        __syncthreads();
    }
    const float inv = 1.f / red[0];

#pragma unroll
    for (int c = 0; c < 8; c++) {
        int i = threadIdx.x + c * 256;
        if (i < len) pr[off + i] = __float2half(rv[c] * inv);
    }
    const int zend = min(T_DIM, ((t >> 7) + 1) << 7);
    const __half z = __float2half(0.f);
    for (int i = len + threadIdx.x; i < zend; i += 256) pr[off + i] = z;
}

// ---------------- launch ------------------------------------------------------
#define SYM(p, s) cudaGetSymbolAddress((void**)&p, s)

extern "C" void kernel_launch(void* const* d_in, const int* in_sizes, int n_in,
                              void* d_out, int out_size)
{
    const float* hidden    = (const float*)d_in[0];
    const int*   positions = (const int*)d_in[1];
    const float* w_q_a     = (const float*)d_in[2];
    const float* q_a_ln_w  = (const float*)d_in[3];
    const float* w_q_b     = (const float*)d_in[4];
    const float* w_kv_a    = (const float*)d_in[5];
    const float* kv_a_ln_w = (const float*)d_in[6];
    const float* w_kc      = (const float*)d_in[7];
    const float* w_vc      = (const float*)d_in[8];
    const float* w_o       = (const float*)d_in[9];
    float*       out       = (float*)d_out;

    float *qalat, *kin, *cs, *scores;
    SYM(qalat, g_qalat); SYM(kin, g_kin); SYM(cs, g_cs); SYM(scores, g_scores);

    __nv_bfloat16 *hid_h,*hid_l, *wqkvT_h,*wqkvT_l, *qan_h,*qan_l, *wqbT_h,*wqbT_l,
                  *qpr_h,*qpr_l, *wkcT_h,*wkcT_l, *qin_h,*qin_l,
                  *kin_h,*kin_l, *ctx_h,*ctx_l,
                  *wvcT_h,*wvcT_l, *att_h,*att_l, *woT_h,*woT_l;
    __half *pr16, *vT16_h, *vT16_l;
    SYM(hid_h,b_hid_h);     SYM(hid_l,b_hid_l);
    SYM(wqkvT_h,b_wqkvT_h); SYM(wqkvT_l,b_wqkvT_l);
    SYM(qan_h,b_qan_h);     SYM(qan_l,b_qan_l);
    SYM(wqbT_h,b_wqbT_h);   SYM(wqbT_l,b_wqbT_l);
    SYM(qpr_h,b_qproj_h);   SYM(qpr_l,b_qproj_l);
    SYM(wkcT_h,b_wkcT_h);   SYM(wkcT_l,b_wkcT_l);
    SYM(qin_h,b_qin_h);     SYM(qin_l,b_qin_l);
    SYM(kin_h,b_kin_h);     SYM(kin_l,b_kin_l);
    SYM(ctx_h,b_ctx_h);     SYM(ctx_l,b_ctx_l);
    SYM(wvcT_h,b_wvcT_h);   SYM(wvcT_l,b_wvcT_l);
    SYM(att_h,b_attn_h);    SYM(att_l,b_attn_l);
    SYM(woT_h,b_woT_h);     SYM(woT_l,b_woT_l);
    SYM(pr16, h_probs);     SYM(vT16_h, h_vT_h);  SYM(vT16_l, h_vT_l);

    cudaFuncSetAttribute(gemm_bf16<0,false>, cudaFuncAttributeMaxDynamicSharedMemorySize, SMEM_BYTES);
    cudaFuncSetAttribute(gemm_bf16<0,true >, cudaFuncAttributeMaxDynamicSharedMemorySize, SMEM_BYTES);
    cudaFuncSetAttribute(gemm_bf16<1,false>, cudaFuncAttributeMaxDynamicSharedMemorySize, SMEM_BYTES);
    cudaFuncSetAttribute(gemm_f16<2>, cudaFuncAttributeMaxDynamicSharedMemorySize, F16_SMEM_BYTES);

    dim3 tb(32, 8);

    // ---- operand conversion (weights + hidden) ----
    convert_row_split<<<10240, 256>>>(hidden, hid_h, hid_l);
    transpose_split<<<dim3(48, 160, 1), tb>>>(w_q_a, QLR, HID, QLR, wqkvT_h, wqkvT_l, 0, 0);
    transpose_split<<<dim3(18, 160, 1), tb>>>(w_kv_a, DQK, HID, DQK,
                                              wqkvT_h + (long long)QLR * HID,
                                              wqkvT_l + (long long)QLR * HID, 0, 0);
    transpose_split<<<dim3(192, 48, 1), tb>>>(w_q_b, H_HEADS*QKD, QLR, H_HEADS*QKD, wqbT_h, wqbT_l, 0, 0);
    transpose_split<<<dim3(16, 4, H_HEADS), tb>>>(w_kc, KVLR, NOPE, KVLR, wkcT_h, wkcT_l,
                                                  (long long)NOPE*KVLR, (long long)KVLR*NOPE);
    transpose_split<<<dim3(4, 16, H_HEADS), tb>>>(w_vc, VDIM, KVLR, VDIM, wvcT_h, wvcT_l,
                                                  (long long)KVLR*VDIM, (long long)VDIM*KVLR);
    transpose_split<<<dim3(160, 128, 1), tb>>>(w_o, HID, H_HEADS*VDIM, HID, woT_h, woT_l, 0, 0);

    // 1+4. [q_a | latent] = hidden @ [w_q_a | w_kv_a]  (merged, fp32 out)
    gemm_bf16<0,false><<<dim3(17, 16, 1), 256, SMEM_BYTES>>>(
        hid_h, hid_l, wqkvT_h, wqkvT_l, qalat, nullptr, nullptr,
        T_DIM, QKV_N, HID, HID, HID, QKV_N, 0, 0, 0, 1.f);
    // 2. rmsnorm(q_a) -> split
    rmsnorm_split<<<T_DIM, 256>>>(qalat, QKV_N, q_a_ln_w, qan_h, qan_l, QLR);
    // 5. k_input (fp32 + split) + cos/sin; vT fp16 split from fp32 kin
    build_k_kernel<<<T_DIM, 256>>>(qalat, kv_a_ln_w, positions, kin, kin_h, kin_l, cs);
    transpose_split_f16<<<dim3(16, 64, 1), tb>>>(kin, DQK, T_DIM, KVLR, vT16_h, vT16_l);
    // 3. qproj = qan @ w_q_b  (split out)
    gemm_bf16<0,true><<<dim3(48, 16, 1), 256, SMEM_BYTES>>>(
        qan_h, qan_l, wqbT_h, wqbT_l, nullptr, qpr_h, qpr_l,
        T_DIM, H_HEADS*QKD, QLR, QLR, QLR, H_HEADS*QKD, 0, 0, 0, 1.f);
    // 6. qin[:, :512] = q_nope @ w_kc  (split out, strided into qin)
    gemm_bf16<0,true><<<dim3(4, 16, H_HEADS), 256, SMEM_BYTES>>>(
        qpr_h, qpr_l, wkcT_h, wkcT_l, nullptr, qin_h, qin_l,
        T_DIM, KVLR, NOPE, H_HEADS*QKD, NOPE, DQK,
        (long long)QKD, (long long)KVLR*NOPE, (long long)T_DIM*DQK, 1.f);
    // 7. qin[:, 512:576] = rope(q_pe)
    rope_q_split<<<dim3(T_DIM, H_HEADS/8), dim3(32, 8)>>>(qpr_h, qpr_l, cs, qin_h, qin_l);
    // 8. scores = SCALE * qin @ kin^T  (causal skip, fp32 out)
    gemm_bf16<1,false><<<dim3(16, 16, H_HEADS), 256, SMEM_BYTES>>>(
        qin_h, qin_l, kin_h, kin_l, scores, nullptr, nullptr,
        T_DIM, T_DIM, DQK, DQK, DQK, T_DIM,
        (long long)T_DIM*DQK, 0, (long long)T_DIM*T_DIM, ATTN_SCALE);
    // 9. softmax -> single fp16 probs
    softmax_f16<<<dim3(T_DIM, H_HEADS), 256>>>(scores, pr16);
    // 10. ctx = probs @ v  (fp16 path: 2 MMAs; K clamped; split-bf16 out)
    gemm_f16<2><<<dim3(4, 16, H_HEADS), 256, F16_SMEM_BYTES>>>(
        pr16, vT16_h, vT16_l, ctx_h, ctx_l,
        T_DIM, KVLR, T_DIM, T_DIM, T_DIM, KVLR,
        (long long)T_DIM*T_DIM, 0, (long long)T_DIM*KVLR, 1.f);
    // 11. attn = ctx @ w_vc  (split out)
    gemm_bf16<0,true><<<dim3(1, 16, H_HEADS), 256, SMEM_BYTES>>>(
        ctx_h, ctx_l, wvcT_h, wvcT_l, nullptr, att_h, att_l,
        T_DIM, VDIM, KVLR, KVLR, KVLR, H_HEADS*VDIM,
        (long long)T_DIM*KVLR, (long long)VDIM*KVLR, (long long)VDIM, 1.f);
    // 12. out = attn @ w_o  (fp32 out)
    gemm_bf16<0,false><<<dim3(40, 16, 1), 256, SMEM_BYTES>>>(
        att_h, att_l, woT_h, woT_l, out, nullptr, nullptr,
        T_DIM, HID, H_HEADS*VDIM, H_HEADS*VDIM, H_HEADS*VDIM, HID, 0, 0, 0, 1.f);
}

// round 17
// speedup vs baseline: 1.0013x; 1.0000x over previous
#include <cuda_runtime.h>
#include <cuda_bf16.h>
#include <cuda_fp16.h>
#include <math.h>
#include <stdint.h>

// ---------------- problem constants ----------------
#define T_DIM   2048
#define HID     5120
#define QLR     1536
#define KVLR    512
#define NOPE    128
#define ROPE_D  64
#define VDIM    128
#define H_HEADS 32
#define QKD     192
#define DQK     576
#define QKV_N   (QLR + DQK)     // 2112
#define ATTN_SCALE 0.07216878364870323f
#define RMS_EPS 1e-6f

#define STAGES 3
#define BK 32
#define ROW_U32 20
#define ROW_BYTES 80
#define ARR_U32 (128 * ROW_U32)               // 2560
#define STAGE_U32 (4 * ARR_U32)               // 10240
#define SMEM_BYTES (STAGES * STAGE_U32 * 4)   // 122880
#define F16_STAGE_U32 (3 * ARR_U32)           // 7680 (A single + Bh + Bl)
#define F16_SMEM_BYTES (STAGES * F16_STAGE_U32 * 4)  // 92160

// ---------------- fp32 scratch ----------------
__device__ float g_qalat [T_DIM * QKV_N];
__device__ float g_kin   [T_DIM * DQK];
__device__ float g_cs    [T_DIM * ROPE_D];
__device__ float g_scores[134217728];       // [H][T][T]

// ---------------- split-bf16 operand storage (hi/lo) ----------------
#define BDECL(name, n) \
    __device__ __align__(16) __nv_bfloat16 name##_h[n]; \
    __device__ __align__(16) __nv_bfloat16 name##_l[n];

BDECL(b_hid,    10485760)
BDECL(b_wqkvT,  10813440)
BDECL(b_qan,     3145728)
BDECL(b_wqbT,    9437184)
BDECL(b_qproj,  12582912)
BDECL(b_wkcT,    2097152)
BDECL(b_qin,    37748736)
BDECL(b_kin,     1179648)
BDECL(b_ctx,    33554432)
BDECL(b_wvcT,    2097152)
BDECL(b_attn,    8388608)
BDECL(b_woT,    20971520)

// ---------------- fp16 probs path storage ----------------
__device__ __align__(16) __half h_probs[134217728];  // [32][2048][2048]
__device__ __align__(16) __half h_vT_h [1048576];    // [512][2048]
__device__ __align__(16) __half h_vT_l [1048576];

// ---------------- helpers ----------------
__device__ __forceinline__ void split1(float x, __nv_bfloat16& h, __nv_bfloat16& l)
{
    h = __float2bfloat16(x);
    l = __float2bfloat16(x - __bfloat162float(h));
}
__device__ __forceinline__ void split1h(float x, __half& h, __half& l)
{
    h = __float2half(x);
    l = __float2half(x - __half2float(h));
}
__device__ __forceinline__ uint32_t packbf(__nv_bfloat16 a, __nv_bfloat16 b)
{
    return (uint32_t)__bfloat16_as_ushort(a) | ((uint32_t)__bfloat16_as_ushort(b) << 16);
}
__device__ __forceinline__ void cp16(void* smem_dst, const void* gsrc)
{
    uint32_t d = (uint32_t)__cvta_generic_to_shared(smem_dst);
    asm volatile("cp.async.ca.shared.global [%0], [%1], 16;" :: "r"(d), "l"(gsrc));
}
#define CP_COMMIT() asm volatile("cp.async.commit_group;")
#define CP_WAIT()   asm volatile("cp.async.wait_group 1;")

#define MMA16816(c, a, b)                                                      \
    asm volatile("mma.sync.aligned.m16n8k16.row.col.f32.bf16.bf16.f32 "        \
                 "{%0,%1,%2,%3},{%4,%5,%6,%7},{%8,%9},{%0,%1,%2,%3};"          \
                 : "+f"((c)[0]), "+f"((c)[1]), "+f"((c)[2]), "+f"((c)[3])      \
                 : "r"((a)[0]), "r"((a)[1]), "r"((a)[2]), "r"((a)[3]),         \
                   "r"((b)[0]), "r"((b)[1]))

#define MMA16816F(c, a, b)                                                     \
    asm volatile("mma.sync.aligned.m16n8k16.row.col.f32.f16.f16.f32 "          \
                 "{%0,%1,%2,%3},{%4,%5,%6,%7},{%8,%9},{%0,%1,%2,%3};"          \
                 : "+f"((c)[0]), "+f"((c)[1]), "+f"((c)[2]), "+f"((c)[3])      \
                 : "r"((a)[0]), "r"((a)[1]), "r"((a)[2]), "r"((a)[3]),         \
                   "r"((b)[0]), "r"((b)[1]))

#define LDSM4(r, a)                                                            \
    asm volatile("ldmatrix.sync.aligned.m8n8.x4.shared.b16 {%0,%1,%2,%3}, [%4];" \
                 : "=r"((r)[0]), "=r"((r)[1]), "=r"((r)[2]), "=r"((r)[3])      \
                 : "r"(a))

// ---------------- split-bf16 TN GEMM (ldmatrix fragments) ----------------
template <int CAUSAL, bool SPLITOUT>
__global__ __launch_bounds__(256)
void gemm_bf16(const __nv_bfloat16* __restrict__ Ah, const __nv_bfloat16* __restrict__ Al,
               const __nv_bfloat16* __restrict__ Bh, const __nv_bfloat16* __restrict__ Bl,
               float* __restrict__ C,
               __nv_bfloat16* __restrict__ CH, __nv_bfloat16* __restrict__ CL,
               int M, int N, int K, int lda, int ldb, int ldc,
               long long sA, long long sB, long long sC, float alpha)
{
    const int m0 = blockIdx.y * 128;
    const int n0 = blockIdx.x * 128;
    if (CAUSAL == 1 && n0 > m0 + 127) return;

    Ah += (long long)blockIdx.z * sA;  Al += (long long)blockIdx.z * sA;
    Bh += (long long)blockIdx.z * sB;  Bl += (long long)blockIdx.z * sB;
    if (SPLITOUT) { CH += (long long)blockIdx.z * sC; CL += (long long)blockIdx.z * sC; }
    else          { C  += (long long)blockIdx.z * sC; }

    const int Keff = (CAUSAL == 2) ? min(K, m0 + 128) : K;
    const int nk = Keff / BK;

    extern __shared__ uint32_t smem_u[];
    const uint32_t sm_base = (uint32_t)__cvta_generic_to_shared(smem_u);

    const int tid  = threadIdx.x;
    const int lane = tid & 31;
    const int warp = tid >> 5;
    const int gid  = lane >> 2;
    const int tig  = lane & 3;
    const int warpM = (warp & 1) * 64;
    const int warpN = (warp >> 1) * 32;

    const int r0 = tid >> 2;
    const int c0 = tid & 3;

    const int q  = lane >> 3;
    const int ri = lane & 7;
    uint32_t aOff[4];
#pragma unroll
    for (int i = 0; i < 4; i++)
        aOff[i] = (uint32_t)((warpM + i * 16 + (q & 1) * 8 + ri) * ROW_BYTES + (q >> 1) * 16);
    uint32_t bOff[2];
#pragma unroll
    for (int jp = 0; jp < 2; jp++)
        bOff[jp] = (uint32_t)((warpN + (2 * jp + (q >> 1)) * 8 + ri) * ROW_BYTES + (q & 1) * 16);

    auto load_stage = [&](int slot, int k0) {
        uint32_t* base = smem_u + slot * STAGE_U32;
#pragma unroll
        for (int u = 0; u < 2; u++) {
            int row = r0 + u * 64;
            int kc  = k0 + c0 * 8;
            uint32_t* dA = base + row * ROW_U32 + c0 * 4;
            cp16(dA,             Ah + (long long)(m0 + row) * lda + kc);
            cp16(dA + ARR_U32,   Al + (long long)(m0 + row) * lda + kc);
            int bn = min(n0 + row, N - 1);
            uint32_t* dB = base + 2 * ARR_U32 + row * ROW_U32 + c0 * 4;
            cp16(dB,             Bh + (long long)bn * ldb + kc);
            cp16(dB + ARR_U32,   Bl + (long long)bn * ldb + kc);
        }
    };

    float acc[4][4][4];
#pragma unroll
    for (int i = 0; i < 4; i++)
#pragma unroll
        for (int j = 0; j < 4; j++)
#pragma unroll
            for (int c = 0; c < 4; c++) acc[i][j][c] = 0.f;

    for (int s = 0; s < STAGES - 1; s++) {
        if (s < nk) load_stage(s, s * BK);
        CP_COMMIT();
    }

    for (int it = 0; it < nk; it++) {
        CP_WAIT();
        __syncthreads();

        if (it + STAGES - 1 < nk)
            load_stage((it + STAGES - 1) % STAGES, (it + STAGES - 1) * BK);
        CP_COMMIT();

        const uint32_t stA_h = sm_base + (it % STAGES) * STAGE_U32 * 4;
        const uint32_t stA_l = stA_h + ARR_U32 * 4;
        const uint32_t stB_h = stA_h + 2 * ARR_U32 * 4;
        const uint32_t stB_l = stA_h + 3 * ARR_U32 * 4;

#pragma unroll
        for (int ks = 0; ks < 2; ks++) {
            const uint32_t cbB = ks * 32;
            uint32_t af[4][4], bh4[4][2], bl4[4][2];
#pragma unroll
            for (int i = 0; i < 4; i++)
                LDSM4(af[i], stA_h + aOff[i] + cbB);
#pragma unroll
            for (int jp = 0; jp < 2; jp++) {
                LDSM4(&bh4[2 * jp][0], stB_h + bOff[jp] + cbB);
                LDSM4(&bl4[2 * jp][0], stB_l + bOff[jp] + cbB);
            }
#pragma unroll
            for (int i = 0; i < 4; i++)
#pragma unroll
                for (int j = 0; j < 4; j++) {
                    MMA16816(acc[i][j], af[i], bh4[j]);
                    MMA16816(acc[i][j], af[i], bl4[j]);
                }
#pragma unroll
            for (int i = 0; i < 4; i++)
                LDSM4(af[i], stA_l + aOff[i] + cbB);
#pragma unroll
            for (int i = 0; i < 4; i++)
#pragma unroll
                for (int j = 0; j < 4; j++)
                    MMA16816(acc[i][j], af[i], bh4[j]);
        }
        __syncthreads();
    }

#pragma unroll
    for (int i = 0; i < 4; i++) {
#pragma unroll
        for (int j = 0; j < 4; j++) {
            int r = m0 + warpM + i * 16 + gid;
            int cn = n0 + warpN + j * 8 + 2 * tig;
            if (cn < N) {
                if (SPLITOUT) {
#pragma unroll
                    for (int rr = 0; rr < 2; rr++) {
                        __nv_bfloat16 h0, l0, h1, l1;
                        split1(acc[i][j][rr * 2 + 0] * alpha, h0, l0);
                        split1(acc[i][j][rr * 2 + 1] * alpha, h1, l1);
                        long long o = (long long)(r + rr * 8) * ldc + cn;
                        *(uint32_t*)(CH + o) = packbf(h0, h1);
                        *(uint32_t*)(CL + o) = packbf(l0, l1);
                    }
                } else {
                    float2 v0 = make_float2(acc[i][j][0] * alpha, acc[i][j][1] * alpha);
                    float2 v1 = make_float2(acc[i][j][2] * alpha, acc[i][j][3] * alpha);
                    *(float2*)(C + (long long)r * ldc + cn)       = v0;
                    *(float2*)(C + (long long)(r + 8) * ldc + cn) = v1;
                }
            }
        }
    }
}

// ---------------- fp16 TN GEMM: A single fp16, B fp16 hi/lo (2 MMAs) --------
// Used for ctx = probs @ v^T. Output split-bf16.
template <int CAUSAL>
__global__ __launch_bounds__(256)
void gemm_f16(const __half* __restrict__ A,
              const __half* __restrict__ Bh, const __half* __restrict__ Bl,
              __nv_bfloat16* __restrict__ CH, __nv_bfloat16* __restrict__ CL,
              int M, int N, int K, int lda, int ldb, int ldc,
              long long sA, long long sB, long long sC, float alpha)
{
    const int m0 = blockIdx.y * 128;
    const int n0 = blockIdx.x * 128;

    A  += (long long)blockIdx.z * sA;
    Bh += (long long)blockIdx.z * sB;  Bl += (long long)blockIdx.z * sB;
    CH += (long long)blockIdx.z * sC;  CL += (long long)blockIdx.z * sC;

    const int Keff = (CAUSAL == 2) ? min(K, m0 + 128) : K;
    const int nk = Keff / BK;

    extern __shared__ uint32_t smem_u[];
    const uint32_t sm_base = (uint32_t)__cvta_generic_to_shared(smem_u);

    const int tid  = threadIdx.x;
    const int lane = tid & 31;
    const int warp = tid >> 5;
    const int gid  = lane >> 2;
    const int tig  = lane & 3;
    const int warpM = (warp & 1) * 64;
    const int warpN = (warp >> 1) * 32;

    const int r0 = tid >> 2;
    const int c0 = tid & 3;

    const int q  = lane >> 3;
    const int ri = lane & 7;
    uint32_t aOff[4];
#pragma unroll
    for (int i = 0; i < 4; i++)
        aOff[i] = (uint32_t)((warpM + i * 16 + (q & 1) * 8 + ri) * ROW_BYTES + (q >> 1) * 16);
    uint32_t bOff[2];
#pragma unroll
    for (int jp = 0; jp < 2; jp++)
        bOff[jp] = (uint32_t)((warpN + (2 * jp + (q >> 1)) * 8 + ri) * ROW_BYTES + (q & 1) * 16);

    auto load_stage = [&](int slot, int k0) {
        uint32_t* base = smem_u + slot * F16_STAGE_U32;
#pragma unroll
        for (int u = 0; u < 2; u++) {
            int row = r0 + u * 64;
            int kc  = k0 + c0 * 8;
            uint32_t* dA = base + row * ROW_U32 + c0 * 4;
            cp16(dA, A + (long long)(m0 + row) * lda + kc);
            int bn = min(n0 + row, N - 1);
            uint32_t* dB = base + ARR_U32 + row * ROW_U32 + c0 * 4;
            cp16(dB,             Bh + (long long)bn * ldb + kc);
            cp16(dB + ARR_U32,   Bl + (long long)bn * ldb + kc);
        }
    };

    float acc[4][4][4];
#pragma unroll
    for (int i = 0; i < 4; i++)
#pragma unroll
        for (int j = 0; j < 4; j++)
#pragma unroll
            for (int c = 0; c < 4; c++) acc[i][j][c] = 0.f;

    for (int s = 0; s < STAGES - 1; s++) {
        if (s < nk) load_stage(s, s * BK);
        CP_COMMIT();
    }

    for (int it = 0; it < nk; it++) {
        CP_WAIT();
        __syncthreads();

        if (it + STAGES - 1 < nk)
            load_stage((it + STAGES - 1) % STAGES, (it + STAGES - 1) * BK);
        CP_COMMIT();

        const uint32_t stA   = sm_base + (it % STAGES) * F16_STAGE_U32 * 4;
        const uint32_t stB_h = stA + ARR_U32 * 4;
        const uint32_t stB_l = stA + 2 * ARR_U32 * 4;

#pragma unroll
        for (int ks = 0; ks < 2; ks++) {
            const uint32_t cbB = ks * 32;
            uint32_t af[4][4], bh4[4][2], bl4[4][2];
#pragma unroll
            for (int i = 0; i < 4; i++)
                LDSM4(af[i], stA + aOff[i] + cbB);
#pragma unroll
            for (int jp = 0; jp < 2; jp++) {
                LDSM4(&bh4[2 * jp][0], stB_h + bOff[jp] + cbB);
                LDSM4(&bl4[2 * jp][0], stB_l + bOff[jp] + cbB);
            }
#pragma unroll
            for (int i = 0; i < 4; i++)
#pragma unroll
                for (int j = 0; j < 4; j++) {
                    MMA16816F(acc[i][j], af[i], bh4[j]);
                    MMA16816F(acc[i][j], af[i], bl4[j]);
                }
        }
        __syncthreads();
    }

#pragma unroll
    for (int i = 0; i < 4; i++) {
#pragma unroll
        for (int j = 0; j < 4; j++) {
            int r = m0 + warpM + i * 16 + gid;
            int cn = n0 + warpN + j * 8 + 2 * tig;
            if (cn < N) {
#pragma unroll
                for (int rr = 0; rr < 2; rr++) {
                    __nv_bfloat16 h0, l0, h1, l1;
                    split1(acc[i][j][rr * 2 + 0] * alpha, h0, l0);
                    split1(acc[i][j][rr * 2 + 1] * alpha, h1, l1);
                    long long o = (long long)(r + rr * 8) * ldc + cn;
                    *(uint32_t*)(CH + o) = packbf(h0, h1);
                    *(uint32_t*)(CL + o) = packbf(l0, l1);
                }
            }
        }
    }
}

// ---------------- convert: fp32 row-major -> split bf16 ----------------------
__global__ void convert_row_split(const float* __restrict__ in,
                                  __nv_bfloat16* __restrict__ oh,
                                  __nv_bfloat16* __restrict__ ol)
{
    long long idx = ((long long)blockIdx.x * 256 + threadIdx.x) * 4;
    float4 f = *(const float4*)(in + idx);
    __nv_bfloat16 h[4], l[4];
    split1(f.x, h[0], l[0]); split1(f.y, h[1], l[1]);
    split1(f.z, h[2], l[2]); split1(f.w, h[3], l[3]);
    *(uint2*)(oh + idx) = *(uint2*)h;
    *(uint2*)(ol + idx) = *(uint2*)l;
}

// ---------------- transpose: fp32 [R][C] -> split bf16 [C][R] ----------------
__global__ void transpose_split(const float* __restrict__ in, int ldin,
                                int R, int Ccols,
                                __nv_bfloat16* __restrict__ oh,
                                __nv_bfloat16* __restrict__ ol,
                                long long sIn, long long sOut)
{
    __shared__ float tile[32][33];
    in += (long long)blockIdx.z * sIn;
    oh += (long long)blockIdx.z * sOut;
    ol += (long long)blockIdx.z * sOut;
    const int cb = blockIdx.x * 32;
    const int rb = blockIdx.y * 32;
#pragma unroll
    for (int i = 0; i < 4; i++) {
        int r = rb + threadIdx.y + i * 8;
        int c = cb + threadIdx.x;
        tile[threadIdx.y + i * 8][threadIdx.x] =
            (r < R && c < Ccols) ? in[(long long)r * ldin + c] : 0.f;
    }
    __syncthreads();
#pragma unroll
    for (int i = 0; i < 4; i++) {
        int c = cb + threadIdx.y + i * 8;
        int r = rb + threadIdx.x;
        if (c < Ccols && r < R) {
            __nv_bfloat16 h, l;
            split1(tile[threadIdx.x][threadIdx.y + i * 8], h, l);
            oh[(long long)c * R + r] = h;
            ol[(long long)c * R + r] = l;
        }
    }
}

// ---------------- transpose: fp32 [R][C] -> split fp16 [C][R] ----------------
__global__ void transpose_split_f16(const float* __restrict__ in, int ldin,
                                    int R, int Ccols,
                                    __half* __restrict__ oh,
                                    __half* __restrict__ ol)
{
    __shared__ float tile[32][33];
    const int cb = blockIdx.x * 32;
    const int rb = blockIdx.y * 32;
#pragma unroll
    for (int i = 0; i < 4; i++) {
        int r = rb + threadIdx.y + i * 8;
        int c = cb + threadIdx.x;
        tile[threadIdx.y + i * 8][threadIdx.x] =
            (r < R && c < Ccols) ? in[(long long)r * ldin + c] : 0.f;
    }
    __syncthreads();
#pragma unroll
    for (int i = 0; i < 4; i++) {
        int c = cb + threadIdx.y + i * 8;
        int r = rb + threadIdx.x;
        if (c < Ccols && r < R) {
            __half h, l;
            split1h(tile[threadIdx.x][threadIdx.y + i * 8], h, l);
            oh[(long long)c * R + r] = h;
            ol[(long long)c * R + r] = l;
        }
    }
}

// ---------------- RMSNorm (strided input) with fused split output ------------
__global__ void rmsnorm_split(const float* __restrict__ x, int ldx,
                              const float* __restrict__ w,
                              __nv_bfloat16* __restrict__ yh,
                              __nv_bfloat16* __restrict__ yl, int D)
{
    const int row = blockIdx.x;
    const float* xr = x + (long long)row * ldx;

    float ss = 0.f;
    for (int i = threadIdx.x; i < D; i += 256) { float v = xr[i]; ss += v * v; }
    __shared__ float red[256];
    red[threadIdx.x] = ss;
    __syncthreads();
    for (int s = 128; s > 0; s >>= 1) {
        if (threadIdx.x < s) red[threadIdx.x] += red[threadIdx.x + s];
        __syncthreads();
    }
    const float r = rsqrtf(red[0] / (float)D + RMS_EPS);
    for (int i = threadIdx.x; i < D; i += 256) {
        __nv_bfloat16 h, l;
        split1(xr[i] * r * w[i], h, l);
        yh[(long long)row * D + i] = h;
        yl[(long long)row * D + i] = l;
    }
}

// ---------------- build k_input (fp32 + split) + cos/sin ---------------------
__global__ void build_k_kernel(const float* __restrict__ qalat,
                               const float* __restrict__ w,
                               const int* __restrict__ pos32,
                               float* __restrict__ kin,
                               __nv_bfloat16* __restrict__ kh,
                               __nv_bfloat16* __restrict__ kl,
                               float* __restrict__ cs)
{
    const int t = blockIdx.x;
    const float* lr = qalat + (long long)t * QKV_N + QLR;
    float* kr       = kin   + (long long)t * DQK;

    float ss = 0.f;
    for (int i = threadIdx.x; i < KVLR; i += 256) { float v = lr[i]; ss += v * v; }
    __shared__ float red[256];
    red[threadIdx.x] = ss;
    __syncthreads();
    for (int s = 128; s > 0; s >>= 1) {
        if (threadIdx.x < s) red[threadIdx.x] += red[threadIdx.x + s];
        __syncthreads();
    }
    const float r = rsqrtf(red[0] / (float)KVLR + RMS_EPS);
    for (int i = threadIdx.x; i < KVLR; i += 256) {
        float v = lr[i] * r * w[i];
        kr[i] = v;
        __nv_bfloat16 h, l;
        split1(v, h, l);
        kh[(long long)t * DQK + i] = h;
        kl[(long long)t * DQK + i] = l;
    }

    if (threadIdx.x < 32) {
        const int j = threadIdx.x;
        const bool is64 = (pos32[1] == 0);
        const long long p = is64 ? ((const long long*)pos32)[t]
                                 : (long long)pos32[t];
        const double inv = pow(10000.0, -(double)(2 * j) / (double)ROPE_D);
        const double ang = (double)p * inv;
        const float c = (float)cos(ang);
        const float s = (float)sin(ang);
        cs[t * ROPE_D + j]      = c;
        cs[t * ROPE_D + 32 + j] = s;
        const float x1 = lr[KVLR + 2 * j];
        const float x2 = lr[KVLR + 2 * j + 1];
        float o1 = x1 * c - x2 * s;
        float o2 = x2 * c + x1 * s;
        kr[KVLR + 2 * j]     = o1;
        kr[KVLR + 2 * j + 1] = o2;
        __nv_bfloat16 h0, l0, h1, l1;
        split1(o1, h0, l0); split1(o2, h1, l1);
        *(uint32_t*)(kh + (long long)t * DQK + KVLR + 2 * j) = packbf(h0, h1);
        *(uint32_t*)(kl + (long long)t * DQK + KVLR + 2 * j) = packbf(l0, l1);
    }
}

// ---------------- rope q_pe: split qproj -> split qin[.., 512:576] -----------
__global__ void rope_q_split(const __nv_bfloat16* __restrict__ qh,
                             const __nv_bfloat16* __restrict__ ql,
                             const float* __restrict__ cs,
                             __nv_bfloat16* __restrict__ oh,
                             __nv_bfloat16* __restrict__ ol)
{
    const int t = blockIdx.x;
    const int h = blockIdx.y * blockDim.y + threadIdx.y;
    const int j = threadIdx.x;

    const float c = cs[t * ROPE_D + j];
    const float s = cs[t * ROPE_D + 32 + j];
    long long qoff = (long long)t * (H_HEADS * QKD) + h * QKD + NOPE + 2 * j;
    uint32_t ph = *(const uint32_t*)(qh + qoff);
    uint32_t pl = *(const uint32_t*)(ql + qoff);
    float x1 = __bfloat162float(__ushort_as_bfloat16((unsigned short)(ph & 0xFFFF)))
             + __bfloat162float(__ushort_as_bfloat16((unsigned short)(pl & 0xFFFF)));
    float x2 = __bfloat162float(__ushort_as_bfloat16((unsigned short)(ph >> 16)))
             + __bfloat162float(__ushort_as_bfloat16((unsigned short)(pl >> 16)));
    float o1 = x1 * c - x2 * s;
    float o2 = x2 * c + x1 * s;
    __nv_bfloat16 h0, l0, h1, l1;
    split1(o1, h0, l0); split1(o2, h1, l1);
    long long o = ((long long)h * T_DIM + t) * DQK + KVLR + 2 * j;
    *(uint32_t*)(oh + o) = packbf(h0, h1);
    *(uint32_t*)(ol + o) = packbf(l0, l1);
}

// ---------------- causal softmax (register-cached) -> single fp16 ------------
__global__ void softmax_f16(const float* __restrict__ scores,
                            __half* __restrict__ pr)
{
    const int t = blockIdx.x;
    const int h = blockIdx.y;
    const long long off = ((long long)h * T_DIM + t) * T_DIM;
    const float* row = scores + off;
    const int len = t + 1;

    __shared__ float red[256];
    float rv[8];

#pragma unroll
    for (int c = 0; c < 8; c++) {
        int i = threadIdx.x + c * 256;
        rv[c] = (i < len) ? row[i] : -1e30f;
    }
    float mx = rv[0];
#pragma unroll
    for (int c = 1; c < 8; c++) mx = fmaxf(mx, rv[c]);
    red[threadIdx.x] = mx;
    __syncthreads();
    for (int s = 128; s > 0; s >>= 1) {
        if (threadIdx.x < s) red[threadIdx.x] = fmaxf(red[threadIdx.x], red[threadIdx.x + s]);
        __syncthreads();
    }
    mx = red[0];
    __syncthreads();

    float sum = 0.f;
#pragma unroll
    for (int c = 0; c < 8; c++) {
        int i = threadIdx.x + c * 256;
        rv[c] = (i < len) ? expf(rv[c] - mx) : 0.f;
        sum += rv[c];
    }
    red[threadIdx.x] = sum;
    __syncthreads();
    for (int s = 128; s > 0; s >>= 1) {
        if (threadIdx.x < s) red[threadIdx.x] += red[threadIdx.x + s];
        __syncthreads();
    }
    const float inv = 1.f / red[0];

#pragma unroll
    for (int c = 0; c < 8; c++) {
        int i = threadIdx.x + c * 256;
        if (i < len) pr[off + i] = __float2half(rv[c] * inv);
    }
    const int zend = min(T_DIM, ((t >> 7) + 1) << 7);
    const __half z = __float2half(0.f);
    for (int i = len + threadIdx.x; i < zend; i += 256) pr[off + i] = z;
}

// ---------------- launch ------------------------------------------------------
#define SYM(p, s) cudaGetSymbolAddress((void**)&p, s)

extern "C" void kernel_launch(void* const* d_in, const int* in_sizes, int n_in,
                              void* d_out, int out_size)
{
    const float* hidden    = (const float*)d_in[0];
    const int*   positions = (const int*)d_in[1];
    const float* w_q_a     = (const float*)d_in[2];
    const float* q_a_ln_w  = (const float*)d_in[3];
    const float* w_q_b     = (const float*)d_in[4];
    const float* w_kv_a    = (const float*)d_in[5];
    const float* kv_a_ln_w = (const float*)d_in[6];
    const float* w_kc      = (const float*)d_in[7];
    const float* w_vc      = (const float*)d_in[8];
    const float* w_o       = (const float*)d_in[9];
    float*       out       = (float*)d_out;

    float *qalat, *kin, *cs, *scores;
    SYM(qalat, g_qalat); SYM(kin, g_kin); SYM(cs, g_cs); SYM(scores, g_scores);

    __nv_bfloat16 *hid_h,*hid_l, *wqkvT_h,*wqkvT_l, *qan_h,*qan_l, *wqbT_h,*wqbT_l,
                  *qpr_h,*qpr_l, *wkcT_h,*wkcT_l, *qin_h,*qin_l,
                  *kin_h,*kin_l, *ctx_h,*ctx_l,
                  *wvcT_h,*wvcT_l, *att_h,*att_l, *woT_h,*woT_l;
    __half *pr16, *vT16_h, *vT16_l;
    SYM(hid_h,b_hid_h);     SYM(hid_l,b_hid_l);
    SYM(wqkvT_h,b_wqkvT_h); SYM(wqkvT_l,b_wqkvT_l);
    SYM(qan_h,b_qan_h);     SYM(qan_l,b_qan_l);
    SYM(wqbT_h,b_wqbT_h);   SYM(wqbT_l,b_wqbT_l);
    SYM(qpr_h,b_qproj_h);   SYM(qpr_l,b_qproj_l);
    SYM(wkcT_h,b_wkcT_h);   SYM(wkcT_l,b_wkcT_l);
    SYM(qin_h,b_qin_h);     SYM(qin_l,b_qin_l);
    SYM(kin_h,b_kin_h);     SYM(kin_l,b_kin_l);
    SYM(ctx_h,b_ctx_h);     SYM(ctx_l,b_ctx_l);
    SYM(wvcT_h,b_wvcT_h);   SYM(wvcT_l,b_wvcT_l);
    SYM(att_h,b_attn_h);    SYM(att_l,b_attn_l);
    SYM(woT_h,b_woT_h);     SYM(woT_l,b_woT_l);
    SYM(pr16, h_probs);     SYM(vT16_h, h_vT_h);  SYM(vT16_l, h_vT_l);

    cudaFuncSetAttribute(gemm_bf16<0,false>, cudaFuncAttributeMaxDynamicSharedMemorySize, SMEM_BYTES);
    cudaFuncSetAttribute(gemm_bf16<0,true >, cudaFuncAttributeMaxDynamicSharedMemorySize, SMEM_BYTES);
    cudaFuncSetAttribute(gemm_bf16<1,false>, cudaFuncAttributeMaxDynamicSharedMemorySize, SMEM_BYTES);
    cudaFuncSetAttribute(gemm_f16<2>, cudaFuncAttributeMaxDynamicSharedMemorySize, F16_SMEM_BYTES);

    dim3 tb(32, 8);

    // ---- operand conversion (weights + hidden) ----
    convert_row_split<<<10240, 256>>>(hidden, hid_h, hid_l);
    transpose_split<<<dim3(48, 160, 1), tb>>>(w_q_a, QLR, HID, QLR, wqkvT_h, wqkvT_l, 0, 0);
    transpose_split<<<dim3(18, 160, 1), tb>>>(w_kv_a, DQK, HID, DQK,
                                              wqkvT_h + (long long)QLR * HID,
                                              wqkvT_l + (long long)QLR * HID, 0, 0);
    transpose_split<<<dim3(192, 48, 1), tb>>>(w_q_b, H_HEADS*QKD, QLR, H_HEADS*QKD, wqbT_h, wqbT_l, 0, 0);
    transpose_split<<<dim3(16, 4, H_HEADS), tb>>>(w_kc, KVLR, NOPE, KVLR, wkcT_h, wkcT_l,
                                                  (long long)NOPE*KVLR, (long long)KVLR*NOPE);
    transpose_split<<<dim3(4, 16, H_HEADS), tb>>>(w_vc, VDIM, KVLR, VDIM, wvcT_h, wvcT_l,
                                                  (long long)KVLR*VDIM, (long long)VDIM*KVLR);
    transpose_split<<<dim3(160, 128, 1), tb>>>(w_o, HID, H_HEADS*VDIM, HID, woT_h, woT_l, 0, 0);

    // 1+4. [q_a | latent] = hidden @ [w_q_a | w_kv_a]  (merged, fp32 out)
    gemm_bf16<0,false><<<dim3(17, 16, 1), 256, SMEM_BYTES>>>(
        hid_h, hid_l, wqkvT_h, wqkvT_l, qalat, nullptr, nullptr,
        T_DIM, QKV_N, HID, HID, HID, QKV_N, 0, 0, 0, 1.f);
    // 2. rmsnorm(q_a) -> split
    rmsnorm_split<<<T_DIM, 256>>>(qalat, QKV_N, q_a_ln_w, qan_h, qan_l, QLR);
    // 5. k_input (fp32 + split) + cos/sin; vT fp16 split from fp32 kin
    build_k_kernel<<<T_DIM, 256>>>(qalat, kv_a_ln_w, positions, kin, kin_h, kin_l, cs);
    transpose_split_f16<<<dim3(16, 64, 1), tb>>>(kin, DQK, T_DIM, KVLR, vT16_h, vT16_l);
    // 3. qproj = qan @ w_q_b  (split out)
    gemm_bf16<0,true><<<dim3(48, 16, 1), 256, SMEM_BYTES>>>(
        qan_h, qan_l, wqbT_h, wqbT_l, nullptr, qpr_h, qpr_l,
        T_DIM, H_HEADS*QKD, QLR, QLR, QLR, H_HEADS*QKD, 0, 0, 0, 1.f);
    // 6. qin[:, :512] = q_nope @ w_kc  (split out, strided into qin)
    gemm_bf16<0,true><<<dim3(4, 16, H_HEADS), 256, SMEM_BYTES>>>(
        qpr_h, qpr_l, wkcT_h, wkcT_l, nullptr, qin_h, qin_l,
        T_DIM, KVLR, NOPE, H_HEADS*QKD, NOPE, DQK,
        (long long)QKD, (long long)KVLR*NOPE, (long long)T_DIM*DQK, 1.f);
    // 7. qin[:, 512:576] = rope(q_pe)
    rope_q_split<<<dim3(T_DIM, H_HEADS/8), dim3(32, 8)>>>(qpr_h, qpr_l, cs, qin_h, qin_l);
    // 8. scores = SCALE * qin @ kin^T  (causal skip, fp32 out)
    gemm_bf16<1,false><<<dim3(16, 16, H_HEADS), 256, SMEM_BYTES>>>(
        qin_h, qin_l, kin_h, kin_l, scores, nullptr, nullptr,
        T_DIM, T_DIM, DQK, DQK, DQK, T_DIM,
        (long long)T_DIM*DQK, 0, (long long)T_DIM*T_DIM, ATTN_SCALE);
    // 9. softmax -> single fp16 probs
    softmax_f16<<<dim3(T_DIM, H_HEADS), 256>>>(scores, pr16);
    // 10. ctx = probs @ v  (fp16 path: 2 MMAs; K clamped; split-bf16 out)
    gemm_f16<2><<<dim3(4, 16, H_HEADS), 256, F16_SMEM_BYTES>>>(
        pr16, vT16_h, vT16_l, ctx_h, ctx_l,
        T_DIM, KVLR, T_DIM, T_DIM, T_DIM, KVLR,
        (long long)T_DIM*T_DIM, 0, (long long)T_DIM*KVLR, 1.f);
    // 11. attn = ctx @ w_vc  (split out)
    gemm_bf16<0,true><<<dim3(1, 16, H_HEADS), 256, SMEM_BYTES>>>(
        ctx_h, ctx_l, wvcT_h, wvcT_l, nullptr, att_h, att_l,
        T_DIM, VDIM, KVLR, KVLR, KVLR, H_HEADS*VDIM,
        (long long)T_DIM*KVLR, (long long)VDIM*KVLR, (long long)VDIM, 1.f);
    // 12. out = attn @ w_o  (fp32 out)
    gemm_bf16<0,false><<<dim3(40, 16, 1), 256, SMEM_BYTES>>>(
        att_h, att_l, woT_h, woT_l, out, nullptr, nullptr,
        T_DIM, HID, H_HEADS*VDIM, H_HEADS*VDIM, H_HEADS*VDIM, HID, 0, 0, 0, 1.f);
}